// round 13
// baseline (speedup 1.0000x reference)
#include <cuda_runtime.h>
#include <cuda_bf16.h>
#include <math.h>
#include <cstdint>

#define HIDN 256
#define NVAR 20
#define NHEAD 8
#define DHEAD 32
#define MTOK 16384          // B*T
#define FFD 1024
#define ATT_SCALE 0.17677669529663687f
#define LN_EPS 1e-5f

// ======================= helpers =======================
__device__ __forceinline__ uint32_t smem_to_u32(const void* p) {
    uint32_t a;
    asm("{ .reg .u64 t; cvta.to.shared.u64 t, %1; cvt.u32.u64 %0, t; }" : "=r"(a) : "l"(p));
    return a;
}
__device__ __forceinline__ void ldm_x4(uint32_t& r0, uint32_t& r1, uint32_t& r2, uint32_t& r3,
                                       uint32_t addr) {
    asm volatile("ldmatrix.sync.aligned.m8n8.x4.shared.b16 {%0,%1,%2,%3}, [%4];"
                 : "=r"(r0), "=r"(r1), "=r"(r2), "=r"(r3) : "r"(addr));
}
__device__ __forceinline__ void mma_bf16(float* c, const uint32_t* a, const uint32_t* b) {
    asm volatile(
        "mma.sync.aligned.m16n8k16.row.col.f32.bf16.bf16.f32 "
        "{%0,%1,%2,%3}, {%4,%5,%6,%7}, {%8,%9}, {%0,%1,%2,%3};"
        : "+f"(c[0]), "+f"(c[1]), "+f"(c[2]), "+f"(c[3])
        : "r"(a[0]), "r"(a[1]), "r"(a[2]), "r"(a[3]), "r"(b[0]), "r"(b[1]));
}
__device__ __forceinline__ void cp16(uint32_t dst, const void* src) {
    asm volatile("cp.async.cg.shared.global [%0], [%1], 16;" :: "r"(dst), "l"(src));
}
#define CP_COMMIT() asm volatile("cp.async.commit_group;" ::: "memory")
#define CP_WAIT0()  asm volatile("cp.async.wait_group 0;" ::: "memory")
__device__ __forceinline__ void split_bf16(float v, __nv_bfloat16& h, __nv_bfloat16& l) {
    h = __float2bfloat16(v);
    l = __float2bfloat16(v - __bfloat162float(h));
}
__device__ __forceinline__ float gelu_exact(float v) {
    return 0.5f * v * (1.0f + erff(v * 0.70710678118654752f));
}

// ======================= scratch =======================
__device__ __align__(256) float g_S[NHEAD * HIDN];
__device__ __align__(256) float g_sbias[NHEAD];
__device__ __align__(256) float g_cbias[HIDN];
__device__ __align__(256) __nv_bfloat16 g_xwh[(size_t)MTOK * 2048];
__device__ __align__(256) __nv_bfloat16 g_xwl[(size_t)MTOK * 2048];
__device__ __align__(256) __nv_bfloat16 g_ctxh[(size_t)MTOK * HIDN];
__device__ __align__(256) __nv_bfloat16 g_ctxl[(size_t)MTOK * HIDN];
__device__ __align__(256) __nv_bfloat16 g_h1h[(size_t)MTOK * HIDN];
__device__ __align__(256) __nv_bfloat16 g_h1l[(size_t)MTOK * HIDN];
__device__ __align__(256) __nv_bfloat16 g_h2h[(size_t)MTOK * FFD];
__device__ __align__(256) __nv_bfloat16 g_h2l[(size_t)MTOK * FFD];
__device__ __align__(256) __nv_bfloat16 g_woT_h[HIDN * HIDN], g_woT_l[HIDN * HIDN];
__device__ __align__(256) __nv_bfloat16 g_w1T_h[FFD * HIDN],  g_w1T_l[FFD * HIDN];
__device__ __align__(256) __nv_bfloat16 g_w2T_h[HIDN * FFD],  g_w2T_l[HIDN * FFD];
__device__ __align__(256) __nv_bfloat16 g_wvT_h[HIDN * HIDN], g_wvT_l[HIDN * HIDN];

// ======================= K0: tiny precompute =======================
__global__ void k_pre(const float* __restrict__ cls, const float* __restrict__ wq,
                      const float* __restrict__ bq, const float* __restrict__ wk,
                      const float* __restrict__ bk, const float* __restrict__ wo,
                      const float* __restrict__ bo, const float* __restrict__ bv) {
    __shared__ float q_s[HIDN];
    int t = threadIdx.x;
    float acc = bq[t];
    for (int c = 0; c < HIDN; c++) acc += cls[c] * wq[c * HIDN + t];
    q_s[t] = acc;
    __syncthreads();
    for (int idx = t; idx < NHEAD * HIDN; idx += 256) {
        int h = idx >> 8, c = idx & 255;
        float s = 0.f;
        #pragma unroll 8
        for (int d = 0; d < DHEAD; d++) s += wk[c * HIDN + h * DHEAD + d] * q_s[h * DHEAD + d];
        g_S[idx] = s;
    }
    if (t < NHEAD) {
        float s = 0.f;
        for (int d = 0; d < DHEAD; d++) s += bk[t * DHEAD + d] * q_s[t * DHEAD + d];
        g_sbias[t] = s;
    }
    float cb = bo[t];
    for (int c = 0; c < HIDN; c++) cb += bv[c] * wo[c * HIDN + t];
    g_cbias[t] = cb;
}

// ======================= tiled weight transpose+split (coalesced) =======================
__global__ void k_wsplit_all(const float* __restrict__ wo, const float* __restrict__ w1,
                             const float* __restrict__ w2, const float* __restrict__ wv) {
    int which = blockIdx.y;
    const float* w;
    __nv_bfloat16 *hi, *lo;
    int K, N;
    if (which == 0)      { w = wo; hi = g_woT_h; lo = g_woT_l; K = HIDN; N = HIDN; }
    else if (which == 1) { w = w1; hi = g_w1T_h; lo = g_w1T_l; K = HIDN; N = FFD; }
    else if (which == 2) { w = w2; hi = g_w2T_h; lo = g_w2T_l; K = FFD;  N = HIDN; }
    else                 { w = wv; hi = g_wvT_h; lo = g_wvT_l; K = HIDN; N = HIDN; }
    int tiles_n = N >> 5, tiles_k = K >> 5;
    int tile = blockIdx.x;
    if (tile >= tiles_n * tiles_k) return;
    int tk = tile / tiles_n, tn = tile % tiles_n;
    __shared__ float s[32][33];
    int t = threadIdx.x;
    #pragma unroll
    for (int i = 0; i < 4; i++) {
        int e = t + i * 256;
        int row = e >> 5, col = e & 31;
        s[row][col] = w[(size_t)(tk * 32 + row) * N + tn * 32 + col];
    }
    __syncthreads();
    #pragma unroll
    for (int i = 0; i < 4; i++) {
        int e = t + i * 256;
        int row = e >> 5, col = e & 31;
        __nv_bfloat16 h, l;
        split_bf16(s[col][row], h, l);
        size_t o = (size_t)(tn * 32 + row) * K + tk * 32 + col;
        hi[o] = h;
        lo[o] = l;
    }
}

// ======================= K1: fused attention -> xw hi/lo =============
#define XROW 260
__global__ void __launch_bounds__(256) k1_attn(const float* __restrict__ x, int mbase) {
    __shared__ float x_s[NVAR * XROW];
    __shared__ float sc_s[NHEAD * NVAR];
    __shared__ float attn_s[NVAR * NHEAD];
    int m = mbase + blockIdx.x;
    int t = threadIdx.x, lane = t & 31, w = t >> 5;
    const float* xb = x + (size_t)m * (NVAR * HIDN);

    #pragma unroll
    for (int i = 0; i < 5; i++) {
        int e4 = t + i * 256;
        float4 val = *(const float4*)(xb + e4 * 4);
        int e = e4 * 4;
        int v = e >> 8, c = e & 255;
        *(float4*)&x_s[v * XROW + c] = val;
    }

    float s_r[8][8];
    #pragma unroll
    for (int hh = 0; hh < 8; hh++) {
        float4 s0 = *(const float4*)&g_S[hh * 256 + lane * 8];
        float4 s1 = *(const float4*)&g_S[hh * 256 + lane * 8 + 4];
        s_r[hh][0] = s0.x; s_r[hh][1] = s0.y; s_r[hh][2] = s0.z; s_r[hh][3] = s0.w;
        s_r[hh][4] = s1.x; s_r[hh][5] = s1.y; s_r[hh][6] = s1.z; s_r[hh][7] = s1.w;
    }
    __syncthreads();

    for (int v = w; v < NVAR; v += 8) {
        float4 xa = *(const float4*)&x_s[v * XROW + lane * 8];
        float4 xc = *(const float4*)&x_s[v * XROW + lane * 8 + 4];
        float xr[8] = {xa.x, xa.y, xa.z, xa.w, xc.x, xc.y, xc.z, xc.w};
        float sums[8];
        #pragma unroll
        for (int hh = 0; hh < 8; hh++) {
            float s = 0.f;
            #pragma unroll
            for (int i = 0; i < 8; i++) s += xr[i] * s_r[hh][i];
            sums[hh] = s;
        }
        #pragma unroll
        for (int hh = 0; hh < 8; hh++) {
            #pragma unroll
            for (int o = 16; o > 0; o >>= 1)
                sums[hh] += __shfl_xor_sync(0xffffffffu, sums[hh], o);
        }
        if (lane == 0) {
            #pragma unroll
            for (int hh = 0; hh < 8; hh++)
                sc_s[hh * NVAR + v] = (sums[hh] + g_sbias[hh]) * ATT_SCALE;
        }
    }
    __syncthreads();

    {
        float my = (lane < NVAR) ? sc_s[w * NVAR + lane] : -1e30f;
        float mx = my;
        #pragma unroll
        for (int o = 16; o > 0; o >>= 1) mx = fmaxf(mx, __shfl_xor_sync(0xffffffffu, mx, o));
        float e = (lane < NVAR) ? __expf(my - mx) : 0.f;
        float s = e;
        #pragma unroll
        for (int o = 16; o > 0; o >>= 1) s += __shfl_xor_sync(0xffffffffu, s, o);
        if (lane < NVAR) attn_s[lane * 8 + w] = e / s;
    }
    __syncthreads();

    float acc[NHEAD] = {};
    #pragma unroll 4
    for (int v = 0; v < NVAR; v++) {
        float xv = x_s[v * XROW + t];
        float4 a0 = *(const float4*)&attn_s[v * 8];
        float4 a1 = *(const float4*)&attn_s[v * 8 + 4];
        acc[0] += a0.x * xv; acc[1] += a0.y * xv; acc[2] += a0.z * xv; acc[3] += a0.w * xv;
        acc[4] += a1.x * xv; acc[5] += a1.y * xv; acc[6] += a1.z * xv; acc[7] += a1.w * xv;
    }
    size_t base = (size_t)m * 2048;
    #pragma unroll
    for (int j = 0; j < NHEAD; j++) {
        __nv_bfloat16 hh, ll;
        split_bf16(acc[j], hh, ll);
        g_xwh[base + j * 256 + t] = hh;
        g_xwl[base + j * 256 + t] = ll;
    }
}

// ======================= per-head ctx MMA GEMM (KC=32, 2-stage, 4 blk/SM) ==========
#define CRS 80
#define CT_STG 25600
#define CT_TOTAL (2 * CT_STG)
__global__ void __launch_bounds__(256, 4) k_mma_ctx(int rowbase) {
    extern __shared__ __align__(16) char smem[];
    uint32_t sb = smem_to_u32(smem);
    int t = threadIdx.x, lane = t & 31, wid = t >> 5;
    int row0 = rowbase + blockIdx.x * 128, h = blockIdx.y;

    float acc[4][4] = {};

    auto load_stage = [&](int ch, int s) {
        int kk = ch * 32;
        uint32_t base = sb + s * CT_STG;
        #pragma unroll
        for (int i = 0; i < 4; i++) {
            int idx = t + i * 256;
            int arr = idx >> 9;
            int rem = idx & 511;
            int row = rem >> 2, seg = rem & 3;
            const __nv_bfloat16* src = arr ? g_xwl : g_xwh;
            size_t gidx = (size_t)(row0 + row) * 2048 + h * 256 + kk + seg * 8;
            cp16(base + arr * 10240 + row * CRS + seg * 16, src + gidx);
        }
        {
            int arr = t >> 7;
            int rem = t & 127;
            int row = rem >> 2, seg = rem & 3;
            const __nv_bfloat16* src = arr ? g_wvT_l : g_wvT_h;
            size_t gidx = (size_t)(h * 32 + row) * HIDN + kk + seg * 8;
            cp16(base + 20480 + arr * 2560 + row * CRS + seg * 16, src + gidx);
        }
    };

    load_stage(0, 0);
    CP_COMMIT();

    for (int ch = 0; ch < 8; ch++) {
        CP_WAIT0();
        __syncthreads();
        if (ch + 1 < 8) { load_stage(ch + 1, (ch + 1) & 1); CP_COMMIT(); }

        uint32_t st = sb + (ch & 1) * CT_STG;
        #pragma unroll
        for (int ks = 0; ks < 2; ks++) {
            uint32_t a_h[4], a_l[4], b_h[4][2], b_l[4][2];
            uint32_t aoff = (uint32_t)((wid * 16 + (lane & 15)) * CRS
                                       + (ks * 16 + ((lane >> 4) << 3)) * 2);
            ldm_x4(a_h[0], a_h[1], a_h[2], a_h[3], st + aoff);
            ldm_x4(a_l[0], a_l[1], a_l[2], a_l[3], st + 10240 + aoff);
            #pragma unroll
            for (int ng = 0; ng < 2; ng++) {
                uint32_t boff = (uint32_t)((ng * 16 + ((lane & 16) >> 1) + (lane & 7)) * CRS
                                           + (ks * 16 + (lane & 8)) * 2);
                ldm_x4(b_h[2 * ng][0], b_h[2 * ng][1], b_h[2 * ng + 1][0], b_h[2 * ng + 1][1],
                       st + 20480 + boff);
                ldm_x4(b_l[2 * ng][0], b_l[2 * ng][1], b_l[2 * ng + 1][0], b_l[2 * ng + 1][1],
                       st + 23040 + boff);
            }
            #pragma unroll
            for (int nt = 0; nt < 4; nt++) {
                mma_bf16(acc[nt], a_h, b_h[nt]);
                mma_bf16(acc[nt], a_h, b_l[nt]);
                mma_bf16(acc[nt], a_l, b_h[nt]);
            }
        }
        __syncthreads();
    }

    int g = lane >> 2, q = lane & 3;
    int m0 = row0 + wid * 16 + g;
    #pragma unroll
    for (int nt = 0; nt < 4; nt++) {
        int n = h * 32 + nt * 8 + q * 2;
        __nv_bfloat16 h0, l0, h1, l1;
        split_bf16(acc[nt][0], h0, l0); split_bf16(acc[nt][1], h1, l1);
        *(__nv_bfloat162*)(g_ctxh + (size_t)m0 * HIDN + n) = __nv_bfloat162(h0, h1);
        *(__nv_bfloat162*)(g_ctxl + (size_t)m0 * HIDN + n) = __nv_bfloat162(l0, l1);
        split_bf16(acc[nt][2], h0, l0); split_bf16(acc[nt][3], h1, l1);
        *(__nv_bfloat162*)(g_ctxh + (size_t)(m0 + 8) * HIDN + n) = __nv_bfloat162(h0, h1);
        *(__nv_bfloat162*)(g_ctxl + (size_t)(m0 + 8) * HIDN + n) = __nv_bfloat162(l0, l1);
    }
}

// ======================= FF1 GEMM 128x128 (cp.async 2-stage) ===============
#define KC2 32
#define RS2 80
#define STG_SZ 40960
#define MM_TOTAL2 (2 * STG_SZ)

__global__ void __launch_bounds__(256, 2) k_mma_ff1(
    const __nv_bfloat16* __restrict__ Ah, const __nv_bfloat16* __restrict__ Al,
    const __nv_bfloat16* __restrict__ Bh, const __nv_bfloat16* __restrict__ Bl,
    const float* __restrict__ bias,
    __nv_bfloat16* __restrict__ outH, __nv_bfloat16* __restrict__ outL,
    int K, int N) {
    extern __shared__ __align__(16) char smem[];
    uint32_t sb = smem_to_u32(smem);
    int t = threadIdx.x, lane = t & 31, wid = t >> 5;
    int wm = wid & 3, wn = wid >> 2;
    int row0 = blockIdx.y * 128, col0 = blockIdx.x * 128;

    float acc[2][8][4] = {};
    const int nch = K / KC2;

    auto load_stage = [&](int ch, int s) {
        int kk = ch * KC2;
        uint32_t sbase = sb + s * STG_SZ;
        #pragma unroll
        for (int i = 0; i < 8; i++) {
            int idx = t + i * 256;
            int arr = idx >> 9;
            int rem = idx & 511;
            int row = rem >> 2, seg = rem & 3;
            const __nv_bfloat16* src = (arr == 0) ? Ah : (arr == 1) ? Al : (arr == 2) ? Bh : Bl;
            size_t g = (size_t)(((arr < 2) ? row0 : col0) + row) * K + kk + seg * 8;
            cp16(sbase + arr * 10240 + row * RS2 + seg * 16, src + g);
        }
    };

    load_stage(0, 0);
    CP_COMMIT();

    for (int ch = 0; ch < nch; ch++) {
        CP_WAIT0();
        __syncthreads();
        if (ch + 1 < nch) { load_stage(ch + 1, (ch + 1) & 1); CP_COMMIT(); }

        uint32_t st = sb + (ch & 1) * STG_SZ;
        #pragma unroll
        for (int ks = 0; ks < 2; ks++) {
            uint32_t a_h[2][4], a_l[2][4];
            #pragma unroll
            for (int mt = 0; mt < 2; mt++) {
                uint32_t off = (uint32_t)((wm * 32 + mt * 16 + (lane & 15)) * RS2
                                          + (ks * 16 + ((lane >> 4) << 3)) * 2);
                ldm_x4(a_h[mt][0], a_h[mt][1], a_h[mt][2], a_h[mt][3], st + off);
                ldm_x4(a_l[mt][0], a_l[mt][1], a_l[mt][2], a_l[mt][3], st + 10240 + off);
            }
            #pragma unroll
            for (int ng = 0; ng < 4; ng++) {
                uint32_t b_h[2][2], b_l[2][2];
                uint32_t off = (uint32_t)((wn * 64 + ng * 16 + ((lane & 16) >> 1) + (lane & 7)) * RS2
                                          + (ks * 16 + (lane & 8)) * 2);
                ldm_x4(b_h[0][0], b_h[0][1], b_h[1][0], b_h[1][1], st + 20480 + off);
                ldm_x4(b_l[0][0], b_l[0][1], b_l[1][0], b_l[1][1], st + 30720 + off);
                #pragma unroll
                for (int mt = 0; mt < 2; mt++) {
                    #pragma unroll
                    for (int sub = 0; sub < 2; sub++) {
                        float* a = acc[mt][ng * 2 + sub];
                        mma_bf16(a, a_h[mt], b_h[sub]);
                        mma_bf16(a, a_h[mt], b_l[sub]);
                        mma_bf16(a, a_l[mt], b_h[sub]);
                    }
                }
            }
        }
        __syncthreads();
    }

    int g = lane >> 2, q = lane & 3;
    #pragma unroll
    for (int mt = 0; mt < 2; mt++) {
        int m0 = row0 + wm * 32 + mt * 16 + g;
        #pragma unroll
        for (int nt = 0; nt < 8; nt++) {
            int n = col0 + wn * 64 + nt * 8 + q * 2;
            float b0 = bias[n], b1 = bias[n + 1];
            float v00 = gelu_exact(acc[mt][nt][0] + b0), v01 = gelu_exact(acc[mt][nt][1] + b1);
            float v10 = gelu_exact(acc[mt][nt][2] + b0), v11 = gelu_exact(acc[mt][nt][3] + b1);
            __nv_bfloat16 h0, l0, h1, l1;
            split_bf16(v00, h0, l0); split_bf16(v01, h1, l1);
            *(__nv_bfloat162*)(outH + (size_t)m0 * N + n) = __nv_bfloat162(h0, h1);
            *(__nv_bfloat162*)(outL + (size_t)m0 * N + n) = __nv_bfloat162(l0, l1);
            split_bf16(v10, h0, l0); split_bf16(v11, h1, l1);
            *(__nv_bfloat162*)(outH + (size_t)(m0 + 8) * N + n) = __nv_bfloat162(h0, h1);
            *(__nv_bfloat162*)(outL + (size_t)(m0 + 8) * N + n) = __nv_bfloat162(l0, l1);
        }
    }
}

// ======================= wide GEMM 64x256 with fused LN epilogue ====================
#define W_STG 51200
#define W_TOTAL 102400
#define OFF_Y 0
#define OFF_RS 69632
#define OFF_RQ 71680
#define OFF_MU 73728
#define OFF_IV 74240
#define OFF_BIAS 74752
#define OFF_LG 75776
#define OFF_LB 76800
#define OFF_WT 77824
#define OFF_BW 98624

template <int MODE2>
__global__ void __launch_bounds__(256, 2) k_mma_w(
    const __nv_bfloat16* __restrict__ Ah, const __nv_bfloat16* __restrict__ Al,
    const __nv_bfloat16* __restrict__ Bh, const __nv_bfloat16* __restrict__ Bl,
    const float* __restrict__ bias, const float* __restrict__ lng,
    const float* __restrict__ lnb, const float* __restrict__ ww,
    const float* __restrict__ bw,
    __nv_bfloat16* __restrict__ outH, __nv_bfloat16* __restrict__ outL,
    float* __restrict__ outW, int K) {
    extern __shared__ __align__(16) char smem[];
    uint32_t sb = smem_to_u32(smem);
    int t = threadIdx.x, lane = t & 31, wid = t >> 5;
    int wm = wid & 1, wn = wid >> 1;
    int row0 = blockIdx.x * 64;

    float acc[2][8][4] = {};
    const int nch = K / 32;

    auto load_stage = [&](int ch, int s) {
        int kk = ch * 32;
        uint32_t sbase = sb + s * W_STG;
        #pragma unroll
        for (int i = 0; i < 2; i++) {
            int idx = t + i * 256;
            int arr = idx >> 8;
            int rem = idx & 255;
            int row = rem >> 2, seg = rem & 3;
            const __nv_bfloat16* src = arr ? Al : Ah;
            size_t g = (size_t)(row0 + row) * K + kk + seg * 8;
            cp16(sbase + arr * 5120 + row * RS2 + seg * 16, src + g);
        }
        #pragma unroll
        for (int i = 0; i < 8; i++) {
            int idx = t + i * 256;
            int arr = idx >> 10;
            int rem = idx & 1023;
            int row = rem >> 2, seg = rem & 3;
            const __nv_bfloat16* src = arr ? Bl : Bh;
            size_t g = (size_t)row * K + kk + seg * 8;
            cp16(sbase + 10240 + arr * 20480 + row * RS2 + seg * 16, src + g);
        }
    };

    load_stage(0, 0);
    CP_COMMIT();

    for (int ch = 0; ch < nch; ch++) {
        CP_WAIT0();
        __syncthreads();
        if (ch + 1 < nch) { load_stage(ch + 1, (ch + 1) & 1); CP_COMMIT(); }

        uint32_t st = sb + (ch & 1) * W_STG;
        #pragma unroll
        for (int ks = 0; ks < 2; ks++) {
            uint32_t a_h[2][4], a_l[2][4];
            #pragma unroll
            for (int mt = 0; mt < 2; mt++) {
                uint32_t off = (uint32_t)((wm * 32 + mt * 16 + (lane & 15)) * RS2
                                          + (ks * 16 + ((lane >> 4) << 3)) * 2);
                ldm_x4(a_h[mt][0], a_h[mt][1], a_h[mt][2], a_h[mt][3], st + off);
                ldm_x4(a_l[mt][0], a_l[mt][1], a_l[mt][2], a_l[mt][3], st + 5120 + off);
            }
            #pragma unroll
            for (int ng = 0; ng < 4; ng++) {
                uint32_t b_h[2][2], b_l[2][2];
                uint32_t off = (uint32_t)((wn * 64 + ng * 16 + ((lane & 16) >> 1) + (lane & 7)) * RS2
                                          + (ks * 16 + (lane & 8)) * 2);
                ldm_x4(b_h[0][0], b_h[0][1], b_h[1][0], b_h[1][1], st + 10240 + off);
                ldm_x4(b_l[0][0], b_l[0][1], b_l[1][0], b_l[1][1], st + 30720 + off);
                #pragma unroll
                for (int mt = 0; mt < 2; mt++) {
                    #pragma unroll
                    for (int sub = 0; sub < 2; sub++) {
                        float* a = acc[mt][ng * 2 + sub];
                        mma_bf16(a, a_h[mt], b_h[sub]);
                        mma_bf16(a, a_h[mt], b_l[sub]);
                        mma_bf16(a, a_l[mt], b_h[sub]);
                    }
                }
            }
        }
        __syncthreads();
    }

    // ---------------- fused epilogue ----------------
    int g = lane >> 2, q = lane & 3;
    float* bias_s = (float*)(smem + OFF_BIAS);
    float* g_s = (float*)(smem + OFF_LG);
    float* b_s = (float*)(smem + OFF_LB);
    float* redS = (float*)(smem + OFF_RS);
    float* redQ = (float*)(smem + OFF_RQ);
    float* mu_s = (float*)(smem + OFF_MU);
    float* iv_s = (float*)(smem + OFF_IV);

    bias_s[t] = bias[t];
    g_s[t] = lng[t];
    b_s[t] = lnb[t];
    if (MODE2 == 1) {
        float* wt = (float*)(smem + OFF_WT);
        for (int idx = t; idx < HIDN * NVAR; idx += 256) {
            int c = idx / NVAR, j = idx % NVAR;
            wt[j * 260 + c] = ww[idx];
        }
        if (t < NVAR) ((float*)(smem + OFF_BW))[t] = bw[t];
    }
    __syncthreads();

    #pragma unroll
    for (int mt = 0; mt < 2; mt++) {
        #pragma unroll
        for (int nt = 0; nt < 8; nt++) {
            int c0 = wn * 64 + nt * 8 + q * 2;
            acc[mt][nt][0] += bias_s[c0];     acc[mt][nt][1] += bias_s[c0 + 1];
            acc[mt][nt][2] += bias_s[c0];     acc[mt][nt][3] += bias_s[c0 + 1];
        }
    }

    #pragma unroll
    for (int mt = 0; mt < 2; mt++) {
        #pragma unroll
        for (int rr = 0; rr < 2; rr++) {
            float s = 0.f;
            #pragma unroll
            for (int nt = 0; nt < 8; nt++) s += acc[mt][nt][rr * 2] + acc[mt][nt][rr * 2 + 1];
            s += __shfl_xor_sync(0xffffffffu, s, 1);
            s += __shfl_xor_sync(0xffffffffu, s, 2);
            int r = wm * 32 + mt * 16 + rr * 8 + g;
            if (q == 0) redS[r * 8 + wn] = s;
        }
    }
    __syncthreads();
    if (t < 64) mu_s[t] = (redS[t * 8] + redS[t * 8 + 1] + redS[t * 8 + 2] + redS[t * 8 + 3]) * (1.f / 256.f);
    __syncthreads();

    #pragma unroll
    for (int mt = 0; mt < 2; mt++) {
        #pragma unroll
        for (int rr = 0; rr < 2; rr++) {
            int r = wm * 32 + mt * 16 + rr * 8 + g;
            float mu = mu_s[r];
            float s = 0.f;
            #pragma unroll
            for (int nt = 0; nt < 8; nt++) {
                float d0 = acc[mt][nt][rr * 2] - mu, d1 = acc[mt][nt][rr * 2 + 1] - mu;
                s += d0 * d0 + d1 * d1;
            }
            s += __shfl_xor_sync(0xffffffffu, s, 1);
            s += __shfl_xor_sync(0xffffffffu, s, 2);
            if (q == 0) redQ[r * 8 + wn] = s;
        }
    }
    __syncthreads();
    if (t < 64) iv_s[t] = rsqrtf((redQ[t * 8] + redQ[t * 8 + 1] + redQ[t * 8 + 2] + redQ[t * 8 + 3]) * (1.f / 256.f) + LN_EPS);
    __syncthreads();

    #pragma unroll
    for (int mt = 0; mt < 2; mt++) {
        #pragma unroll
        for (int rr = 0; rr < 2; rr++) {
            int r = wm * 32 + mt * 16 + rr * 8 + g;
            float mu = mu_s[r], iv = iv_s[r];
            int grow = row0 + r;
            #pragma unroll
            for (int nt = 0; nt < 8; nt++) {
                int c0 = wn * 64 + nt * 8 + q * 2;
                float y0 = (acc[mt][nt][rr * 2] - mu) * iv * g_s[c0] + b_s[c0];
                float y1 = (acc[mt][nt][rr * 2 + 1] - mu) * iv * g_s[c0 + 1] + b_s[c0 + 1];
                if (MODE2 == 0) {
                    __nv_bfloat16 h0, l0, h1, l1;
                    split_bf16(y0, h0, l0); split_bf16(y1, h1, l1);
                    *(__nv_bfloat162*)(outH + (size_t)grow * HIDN + c0) = __nv_bfloat162(h0, h1);
                    *(__nv_bfloat162*)(outL + (size_t)grow * HIDN + c0) = __nv_bfloat162(l0, l1);
                } else {
                    *(float2*)(smem + OFF_Y + (r * 264 + c0) * 4) = make_float2(y0, y1);
                }
            }
        }
    }

    if (MODE2 == 1) {
        __syncthreads();
        float* Y = (float*)(smem + OFF_Y);
        float* wt = (float*)(smem + OFF_WT);
        float* bw_s = (float*)(smem + OFF_BW);
        const size_t WOFF = (size_t)MTOK * HIDN;
        #pragma unroll
        for (int rr2 = 0; rr2 < 8; rr2++) {
            int r = wid * 8 + rr2;
            int m = row0 + r;
            float yv[8];
            #pragma unroll
            for (int i = 0; i < 8; i++) yv[i] = Y[r * 264 + lane + 32 * i];
            float lg[NVAR];
            #pragma unroll
            for (int j = 0; j < NVAR; j++) {
                float s = 0.f;
                #pragma unroll
                for (int i = 0; i < 8; i++) s += yv[i] * wt[j * 260 + lane + 32 * i];
                lg[j] = s;
            }
            #pragma unroll
            for (int j = 0; j < NVAR; j++) {
                #pragma unroll
                for (int o = 16; o > 0; o >>= 1) lg[j] += __shfl_xor_sync(0xffffffffu, lg[j], o);
                lg[j] += bw_s[j];
            }
            float mx = -1e30f;
            #pragma unroll
            for (int j = 0; j < NVAR; j++) mx = fmaxf(mx, lg[j]);
            float sum = 0.f;
            #pragma unroll
            for (int j = 0; j < NVAR; j++) { lg[j] = __expf(lg[j] - mx); sum += lg[j]; }
            float invs = 1.0f / sum;
            float myw = 0.f;
            #pragma unroll
            for (int j = 0; j < NVAR; j++) if (lane == j) myw = lg[j] * invs;
            if (lane < NVAR) outW[WOFF + (size_t)m * NVAR + lane] = myw;
        }
    }
}

// ======================= K_final: weights + x -> vs_output (float4) ==============
__global__ void k_final(const float* __restrict__ x, float* __restrict__ out) {
    int t = threadIdx.x;
    int warp = t >> 5, lane = t & 31;
    const size_t WOFF = (size_t)MTOK * HIDN;
    #pragma unroll
    for (int tk = 0; tk < 2; tk++) {
        int m = blockIdx.x * 16 + warp * 2 + tk;
        float lg[NVAR];
        #pragma unroll
        for (int j = 0; j < NVAR; j++) lg[j] = out[WOFF + (size_t)m * NVAR + j];
        const float* xb = x + (size_t)m * (NVAR * HIDN);
        int c0 = lane * 8;
        float a[8] = {};
        #pragma unroll 4
        for (int vv = 0; vv < NVAR; vv++) {
            float wv = lg[vv];
            float4 p0 = *(const float4*)(xb + vv * HIDN + c0);
            float4 p1 = *(const float4*)(xb + vv * HIDN + c0 + 4);
            a[0] += wv * p0.x; a[1] += wv * p0.y; a[2] += wv * p0.z; a[3] += wv * p0.w;
            a[4] += wv * p1.x; a[5] += wv * p1.y; a[6] += wv * p1.z; a[7] += wv * p1.w;
        }
        *(float4*)(out + (size_t)m * HIDN + c0) = make_float4(a[0], a[1], a[2], a[3]);
        *(float4*)(out + (size_t)m * HIDN + c0 + 4) = make_float4(a[4], a[5], a[6], a[7]);
    }
}

extern "C" void kernel_launch(void* const* d_in, const int* in_sizes, int n_in,
                              void* d_out, int out_size) {
    (void)in_sizes; (void)n_in; (void)out_size;
    const float* x     = (const float*)d_in[0];
    const float* cls   = (const float*)d_in[1];
    const float* wq    = (const float*)d_in[2];
    const float* bq    = (const float*)d_in[3];
    const float* wk    = (const float*)d_in[4];
    const float* bk    = (const float*)d_in[5];
    const float* wv    = (const float*)d_in[6];
    const float* bv    = (const float*)d_in[7];
    const float* wo    = (const float*)d_in[8];
    const float* bo    = (const float*)d_in[9];
    const float* ln1_g = (const float*)d_in[10];
    const float* ln1_b = (const float*)d_in[11];
    const float* w1    = (const float*)d_in[12];
    const float* b1    = (const float*)d_in[13];
    const float* w2    = (const float*)d_in[14];
    const float* b2    = (const float*)d_in[15];
    const float* ln2_g = (const float*)d_in[16];
    const float* ln2_b = (const float*)d_in[17];
    const float* ww    = (const float*)d_in[18];
    const float* bw    = (const float*)d_in[19];
    float* out = (float*)d_out;

    cudaFuncSetAttribute(k_mma_ff1, cudaFuncAttributeMaxDynamicSharedMemorySize, MM_TOTAL2);
    cudaFuncSetAttribute(k_mma_ctx, cudaFuncAttributeMaxDynamicSharedMemorySize, CT_TOTAL);
    cudaFuncSetAttribute(k_mma_w<0>, cudaFuncAttributeMaxDynamicSharedMemorySize, W_TOTAL);
    cudaFuncSetAttribute(k_mma_w<1>, cudaFuncAttributeMaxDynamicSharedMemorySize, W_TOTAL);

    void *p_ctxh, *p_ctxl, *p_h1h, *p_h1l, *p_h2h, *p_h2l, *p_cbias;
    void *p_woh, *p_wol, *p_w1h, *p_w1l, *p_w2h, *p_w2l;
    cudaGetSymbolAddress(&p_ctxh, g_ctxh);  cudaGetSymbolAddress(&p_ctxl, g_ctxl);
    cudaGetSymbolAddress(&p_h1h, g_h1h);    cudaGetSymbolAddress(&p_h1l, g_h1l);
    cudaGetSymbolAddress(&p_h2h, g_h2h);    cudaGetSymbolAddress(&p_h2l, g_h2l);
    cudaGetSymbolAddress(&p_cbias, g_cbias);
    cudaGetSymbolAddress(&p_woh, g_woT_h);  cudaGetSymbolAddress(&p_wol, g_woT_l);
    cudaGetSymbolAddress(&p_w1h, g_w1T_h);  cudaGetSymbolAddress(&p_w1l, g_w1T_l);
    cudaGetSymbolAddress(&p_w2h, g_w2T_h);  cudaGetSymbolAddress(&p_w2l, g_w2T_l);

    k_pre<<<1, 256>>>(cls, wq, bq, wk, bk, wo, bo, bv);
    k_wsplit_all<<<dim3(256, 4), 256>>>(wo, w1, w2, wv);

    // ---- chunked k1 -> ctx (quarters; 33.5 MB xw chunk stays L2-resident) ----
    const int QT = MTOK / 4;   // 4096 tokens
    for (int qc = 0; qc < 4; qc++) {
        k1_attn<<<QT, 256>>>(x, qc * QT);
        k_mma_ctx<<<dim3(QT / 128, NHEAD), 256, CT_TOTAL>>>(qc * QT);
    }

    // o-proj + cbias + LN1 -> h1 hi/lo   (K=256, N=256; ctx 16.8 MB is L2-resident)
    k_mma_w<0><<<MTOK / 64, 256, W_TOTAL>>>(
        (const __nv_bfloat16*)p_ctxh, (const __nv_bfloat16*)p_ctxl,
        (const __nv_bfloat16*)p_woh, (const __nv_bfloat16*)p_wol,
        (const float*)p_cbias, ln1_g, ln1_b, nullptr, nullptr,
        (__nv_bfloat16*)p_h1h, (__nv_bfloat16*)p_h1l, nullptr, HIDN);

    // ---- chunked FF1 -> FF2 (halves; 67 MB h2 chunk stays mostly L2-resident) ----
    const int HT = MTOK / 2;   // 8192 tokens
    for (int hc = 0; hc < 2; hc++) {
        size_t aoff = (size_t)hc * HT * HIDN;
        size_t hoff = (size_t)hc * HT * FFD;
        k_mma_ff1<<<dim3(FFD / 128, HT / 128), 256, MM_TOTAL2>>>(
            (const __nv_bfloat16*)p_h1h + aoff, (const __nv_bfloat16*)p_h1l + aoff,
            (const __nv_bfloat16*)p_w1h, (const __nv_bfloat16*)p_w1l,
            b1, (__nv_bfloat16*)p_h2h + hoff, (__nv_bfloat16*)p_h2l + hoff, HIDN, FFD);
        k_mma_w<1><<<HT / 64, 256, W_TOTAL>>>(
            (const __nv_bfloat16*)p_h2h + hoff, (const __nv_bfloat16*)p_h2l + hoff,
            (const __nv_bfloat16*)p_w2h, (const __nv_bfloat16*)p_w2l,
            b2, ln2_g, ln2_b, ww, bw, nullptr, nullptr,
            out + (size_t)hc * HT * NVAR, FFD);
    }

    k_final<<<MTOK / 16, 256>>>(x, out);
}

// round 15
// speedup vs baseline: 1.1152x; 1.1152x over previous
#include <cuda_runtime.h>
#include <cuda_bf16.h>
#include <math.h>
#include <cstdint>

#define HIDN 256
#define NVAR 20
#define NHEAD 8
#define DHEAD 32
#define MTOK 16384          // B*T
#define FFD 1024
#define ATT_SCALE 0.17677669529663687f
#define LN_EPS 1e-5f

// ======================= helpers =======================
__device__ __forceinline__ uint32_t smem_to_u32(const void* p) {
    uint32_t a;
    asm("{ .reg .u64 t; cvta.to.shared.u64 t, %1; cvt.u32.u64 %0, t; }" : "=r"(a) : "l"(p));
    return a;
}
__device__ __forceinline__ void ldm_x4(uint32_t& r0, uint32_t& r1, uint32_t& r2, uint32_t& r3,
                                       uint32_t addr) {
    asm volatile("ldmatrix.sync.aligned.m8n8.x4.shared.b16 {%0,%1,%2,%3}, [%4];"
                 : "=r"(r0), "=r"(r1), "=r"(r2), "=r"(r3) : "r"(addr));
}
__device__ __forceinline__ void mma_bf16(float* c, const uint32_t* a, const uint32_t* b) {
    asm volatile(
        "mma.sync.aligned.m16n8k16.row.col.f32.bf16.bf16.f32 "
        "{%0,%1,%2,%3}, {%4,%5,%6,%7}, {%8,%9}, {%0,%1,%2,%3};"
        : "+f"(c[0]), "+f"(c[1]), "+f"(c[2]), "+f"(c[3])
        : "r"(a[0]), "r"(a[1]), "r"(a[2]), "r"(a[3]), "r"(b[0]), "r"(b[1]));
}
__device__ __forceinline__ void cp16(uint32_t dst, const void* src) {
    asm volatile("cp.async.cg.shared.global [%0], [%1], 16;" :: "r"(dst), "l"(src));
}
#define CP_COMMIT() asm volatile("cp.async.commit_group;" ::: "memory")
#define CP_WAIT0()  asm volatile("cp.async.wait_group 0;" ::: "memory")
__device__ __forceinline__ void split_bf16(float v, __nv_bfloat16& h, __nv_bfloat16& l) {
    h = __float2bfloat16(v);
    l = __float2bfloat16(v - __bfloat162float(h));
}
__device__ __forceinline__ float gelu_exact(float v) {
    return 0.5f * v * (1.0f + erff(v * 0.70710678118654752f));
}

// ======================= scratch =======================
__device__ __align__(256) float g_S[NHEAD * HIDN];
__device__ __align__(256) float g_sbias[NHEAD];
__device__ __align__(256) float g_cbias[HIDN];
__device__ __align__(256) __nv_bfloat16 g_xwh[(size_t)MTOK * 2048];
__device__ __align__(256) __nv_bfloat16 g_xwl[(size_t)MTOK * 2048];
__device__ __align__(256) __nv_bfloat16 g_ctxh[(size_t)MTOK * HIDN];
__device__ __align__(256) __nv_bfloat16 g_ctxl[(size_t)MTOK * HIDN];
__device__ __align__(256) __nv_bfloat16 g_h1h[(size_t)MTOK * HIDN];
__device__ __align__(256) __nv_bfloat16 g_h1l[(size_t)MTOK * HIDN];
__device__ __align__(256) __nv_bfloat16 g_h2h[(size_t)MTOK * FFD];
__device__ __align__(256) __nv_bfloat16 g_h2l[(size_t)MTOK * FFD];
__device__ __align__(256) __nv_bfloat16 g_woT_h[HIDN * HIDN], g_woT_l[HIDN * HIDN];
__device__ __align__(256) __nv_bfloat16 g_w1T_h[FFD * HIDN],  g_w1T_l[FFD * HIDN];
__device__ __align__(256) __nv_bfloat16 g_w2T_h[HIDN * FFD],  g_w2T_l[HIDN * FFD];
__device__ __align__(256) __nv_bfloat16 g_wvT_h[HIDN * HIDN], g_wvT_l[HIDN * HIDN];

// ======================= K0: tiny precompute =======================
__global__ void k_pre(const float* __restrict__ cls, const float* __restrict__ wq,
                      const float* __restrict__ bq, const float* __restrict__ wk,
                      const float* __restrict__ bk, const float* __restrict__ wo,
                      const float* __restrict__ bo, const float* __restrict__ bv) {
    __shared__ float q_s[HIDN];
    int t = threadIdx.x;
    float acc = bq[t];
    for (int c = 0; c < HIDN; c++) acc += cls[c] * wq[c * HIDN + t];
    q_s[t] = acc;
    __syncthreads();
    for (int idx = t; idx < NHEAD * HIDN; idx += 256) {
        int h = idx >> 8, c = idx & 255;
        float s = 0.f;
        #pragma unroll 8
        for (int d = 0; d < DHEAD; d++) s += wk[c * HIDN + h * DHEAD + d] * q_s[h * DHEAD + d];
        g_S[idx] = s;
    }
    if (t < NHEAD) {
        float s = 0.f;
        for (int d = 0; d < DHEAD; d++) s += bk[t * DHEAD + d] * q_s[t * DHEAD + d];
        g_sbias[t] = s;
    }
    float cb = bo[t];
    for (int c = 0; c < HIDN; c++) cb += bv[c] * wo[c * HIDN + t];
    g_cbias[t] = cb;
}

// ======================= tiled weight transpose+split (coalesced) =======================
__global__ void k_wsplit_all(const float* __restrict__ wo, const float* __restrict__ w1,
                             const float* __restrict__ w2, const float* __restrict__ wv) {
    int which = blockIdx.y;
    const float* w;
    __nv_bfloat16 *hi, *lo;
    int K, N;
    if (which == 0)      { w = wo; hi = g_woT_h; lo = g_woT_l; K = HIDN; N = HIDN; }
    else if (which == 1) { w = w1; hi = g_w1T_h; lo = g_w1T_l; K = HIDN; N = FFD; }
    else if (which == 2) { w = w2; hi = g_w2T_h; lo = g_w2T_l; K = FFD;  N = HIDN; }
    else                 { w = wv; hi = g_wvT_h; lo = g_wvT_l; K = HIDN; N = HIDN; }
    int tiles_n = N >> 5, tiles_k = K >> 5;
    int tile = blockIdx.x;
    if (tile >= tiles_n * tiles_k) return;
    int tk = tile / tiles_n, tn = tile % tiles_n;
    __shared__ float s[32][33];
    int t = threadIdx.x;
    #pragma unroll
    for (int i = 0; i < 4; i++) {
        int e = t + i * 256;
        int row = e >> 5, col = e & 31;
        s[row][col] = w[(size_t)(tk * 32 + row) * N + tn * 32 + col];
    }
    __syncthreads();
    #pragma unroll
    for (int i = 0; i < 4; i++) {
        int e = t + i * 256;
        int row = e >> 5, col = e & 31;
        __nv_bfloat16 h, l;
        split_bf16(s[col][row], h, l);
        size_t o = (size_t)(tn * 32 + row) * K + tk * 32 + col;
        hi[o] = h;
        lo[o] = l;
    }
}

// ======================= K1: fused attention -> xw hi/lo =============
#define XROW 260
__global__ void __launch_bounds__(256) k1_attn(const float* __restrict__ x) {
    __shared__ float x_s[NVAR * XROW];
    __shared__ float sc_s[NHEAD * NVAR];
    __shared__ float attn_s[NVAR * NHEAD];
    int m = blockIdx.x;
    int t = threadIdx.x, lane = t & 31, w = t >> 5;
    const float* xb = x + (size_t)m * (NVAR * HIDN);

    #pragma unroll
    for (int i = 0; i < 5; i++) {
        int e4 = t + i * 256;
        float4 val = *(const float4*)(xb + e4 * 4);
        int e = e4 * 4;
        int v = e >> 8, c = e & 255;
        *(float4*)&x_s[v * XROW + c] = val;
    }

    float s_r[8][8];
    #pragma unroll
    for (int hh = 0; hh < 8; hh++) {
        float4 s0 = *(const float4*)&g_S[hh * 256 + lane * 8];
        float4 s1 = *(const float4*)&g_S[hh * 256 + lane * 8 + 4];
        s_r[hh][0] = s0.x; s_r[hh][1] = s0.y; s_r[hh][2] = s0.z; s_r[hh][3] = s0.w;
        s_r[hh][4] = s1.x; s_r[hh][5] = s1.y; s_r[hh][6] = s1.z; s_r[hh][7] = s1.w;
    }
    __syncthreads();

    for (int v = w; v < NVAR; v += 8) {
        float4 xa = *(const float4*)&x_s[v * XROW + lane * 8];
        float4 xc = *(const float4*)&x_s[v * XROW + lane * 8 + 4];
        float xr[8] = {xa.x, xa.y, xa.z, xa.w, xc.x, xc.y, xc.z, xc.w};
        float sums[8];
        #pragma unroll
        for (int hh = 0; hh < 8; hh++) {
            float s = 0.f;
            #pragma unroll
            for (int i = 0; i < 8; i++) s += xr[i] * s_r[hh][i];
            sums[hh] = s;
        }
        #pragma unroll
        for (int hh = 0; hh < 8; hh++) {
            #pragma unroll
            for (int o = 16; o > 0; o >>= 1)
                sums[hh] += __shfl_xor_sync(0xffffffffu, sums[hh], o);
        }
        if (lane == 0) {
            #pragma unroll
            for (int hh = 0; hh < 8; hh++)
                sc_s[hh * NVAR + v] = (sums[hh] + g_sbias[hh]) * ATT_SCALE;
        }
    }
    __syncthreads();

    {
        float my = (lane < NVAR) ? sc_s[w * NVAR + lane] : -1e30f;
        float mx = my;
        #pragma unroll
        for (int o = 16; o > 0; o >>= 1) mx = fmaxf(mx, __shfl_xor_sync(0xffffffffu, mx, o));
        float e = (lane < NVAR) ? __expf(my - mx) : 0.f;
        float s = e;
        #pragma unroll
        for (int o = 16; o > 0; o >>= 1) s += __shfl_xor_sync(0xffffffffu, s, o);
        if (lane < NVAR) attn_s[lane * 8 + w] = e / s;
    }
    __syncthreads();

    float acc[NHEAD] = {};
    #pragma unroll 4
    for (int v = 0; v < NVAR; v++) {
        float xv = x_s[v * XROW + t];
        float4 a0 = *(const float4*)&attn_s[v * 8];
        float4 a1 = *(const float4*)&attn_s[v * 8 + 4];
        acc[0] += a0.x * xv; acc[1] += a0.y * xv; acc[2] += a0.z * xv; acc[3] += a0.w * xv;
        acc[4] += a1.x * xv; acc[5] += a1.y * xv; acc[6] += a1.z * xv; acc[7] += a1.w * xv;
    }
    size_t base = (size_t)m * 2048;
    #pragma unroll
    for (int j = 0; j < NHEAD; j++) {
        __nv_bfloat16 hh, ll;
        split_bf16(acc[j], hh, ll);
        g_xwh[base + j * 256 + t] = hh;
        g_xwl[base + j * 256 + t] = ll;
    }
}

// ======================= per-head ctx MMA GEMM (KC=32, 2-stage, 4 blk/SM) ==========
#define CRS 80
#define CT_STG 25600
#define CT_TOTAL (2 * CT_STG)
__global__ void __launch_bounds__(256, 4) k_mma_ctx() {
    extern __shared__ __align__(16) char smem[];
    uint32_t sb = smem_to_u32(smem);
    int t = threadIdx.x, lane = t & 31, wid = t >> 5;
    int row0 = blockIdx.x * 128, h = blockIdx.y;

    float acc[4][4] = {};

    auto load_stage = [&](int ch, int s) {
        int kk = ch * 32;
        uint32_t base = sb + s * CT_STG;
        #pragma unroll
        for (int i = 0; i < 4; i++) {
            int idx = t + i * 256;
            int arr = idx >> 9;
            int rem = idx & 511;
            int row = rem >> 2, seg = rem & 3;
            const __nv_bfloat16* src = arr ? g_xwl : g_xwh;
            size_t gidx = (size_t)(row0 + row) * 2048 + h * 256 + kk + seg * 8;
            cp16(base + arr * 10240 + row * CRS + seg * 16, src + gidx);
        }
        {
            int arr = t >> 7;
            int rem = t & 127;
            int row = rem >> 2, seg = rem & 3;
            const __nv_bfloat16* src = arr ? g_wvT_l : g_wvT_h;
            size_t gidx = (size_t)(h * 32 + row) * HIDN + kk + seg * 8;
            cp16(base + 20480 + arr * 2560 + row * CRS + seg * 16, src + gidx);
        }
    };

    load_stage(0, 0);
    CP_COMMIT();

    for (int ch = 0; ch < 8; ch++) {
        CP_WAIT0();
        __syncthreads();
        if (ch + 1 < 8) { load_stage(ch + 1, (ch + 1) & 1); CP_COMMIT(); }

        uint32_t st = sb + (ch & 1) * CT_STG;
        #pragma unroll
        for (int ks = 0; ks < 2; ks++) {
            uint32_t a_h[4], a_l[4], b_h[4][2], b_l[4][2];
            uint32_t aoff = (uint32_t)((wid * 16 + (lane & 15)) * CRS
                                       + (ks * 16 + ((lane >> 4) << 3)) * 2);
            ldm_x4(a_h[0], a_h[1], a_h[2], a_h[3], st + aoff);
            ldm_x4(a_l[0], a_l[1], a_l[2], a_l[3], st + 10240 + aoff);
            #pragma unroll
            for (int ng = 0; ng < 2; ng++) {
                uint32_t boff = (uint32_t)((ng * 16 + ((lane & 16) >> 1) + (lane & 7)) * CRS
                                           + (ks * 16 + (lane & 8)) * 2);
                ldm_x4(b_h[2 * ng][0], b_h[2 * ng][1], b_h[2 * ng + 1][0], b_h[2 * ng + 1][1],
                       st + 20480 + boff);
                ldm_x4(b_l[2 * ng][0], b_l[2 * ng][1], b_l[2 * ng + 1][0], b_l[2 * ng + 1][1],
                       st + 23040 + boff);
            }
            #pragma unroll
            for (int nt = 0; nt < 4; nt++) {
                mma_bf16(acc[nt], a_h, b_h[nt]);
                mma_bf16(acc[nt], a_h, b_l[nt]);
                mma_bf16(acc[nt], a_l, b_h[nt]);
            }
        }
        __syncthreads();
    }

    int g = lane >> 2, q = lane & 3;
    int m0 = row0 + wid * 16 + g;
    #pragma unroll
    for (int nt = 0; nt < 4; nt++) {
        int n = h * 32 + nt * 8 + q * 2;
        __nv_bfloat16 h0, l0, h1, l1;
        split_bf16(acc[nt][0], h0, l0); split_bf16(acc[nt][1], h1, l1);
        *(__nv_bfloat162*)(g_ctxh + (size_t)m0 * HIDN + n) = __nv_bfloat162(h0, h1);
        *(__nv_bfloat162*)(g_ctxl + (size_t)m0 * HIDN + n) = __nv_bfloat162(l0, l1);
        split_bf16(acc[nt][2], h0, l0); split_bf16(acc[nt][3], h1, l1);
        *(__nv_bfloat162*)(g_ctxh + (size_t)(m0 + 8) * HIDN + n) = __nv_bfloat162(h0, h1);
        *(__nv_bfloat162*)(g_ctxl + (size_t)(m0 + 8) * HIDN + n) = __nv_bfloat162(l0, l1);
    }
}

// ======================= FF1 GEMM 128x128 (cp.async 2-stage) ===============
#define KC2 32
#define RS2 80
#define STG_SZ 40960
#define MM_TOTAL2 (2 * STG_SZ)

__global__ void __launch_bounds__(256, 2) k_mma_ff1(
    const __nv_bfloat16* __restrict__ Ah, const __nv_bfloat16* __restrict__ Al,
    const __nv_bfloat16* __restrict__ Bh, const __nv_bfloat16* __restrict__ Bl,
    const float* __restrict__ bias,
    __nv_bfloat16* __restrict__ outH, __nv_bfloat16* __restrict__ outL,
    int K, int N) {
    extern __shared__ __align__(16) char smem[];
    uint32_t sb = smem_to_u32(smem);
    int t = threadIdx.x, lane = t & 31, wid = t >> 5;
    int wm = wid & 3, wn = wid >> 2;
    int row0 = blockIdx.y * 128, col0 = blockIdx.x * 128;

    float acc[2][8][4] = {};
    const int nch = K / KC2;

    auto load_stage = [&](int ch, int s) {
        int kk = ch * KC2;
        uint32_t sbase = sb + s * STG_SZ;
        #pragma unroll
        for (int i = 0; i < 8; i++) {
            int idx = t + i * 256;
            int arr = idx >> 9;
            int rem = idx & 511;
            int row = rem >> 2, seg = rem & 3;
            const __nv_bfloat16* src = (arr == 0) ? Ah : (arr == 1) ? Al : (arr == 2) ? Bh : Bl;
            size_t g = (size_t)(((arr < 2) ? row0 : col0) + row) * K + kk + seg * 8;
            cp16(sbase + arr * 10240 + row * RS2 + seg * 16, src + g);
        }
    };

    load_stage(0, 0);
    CP_COMMIT();

    for (int ch = 0; ch < nch; ch++) {
        CP_WAIT0();
        __syncthreads();
        if (ch + 1 < nch) { load_stage(ch + 1, (ch + 1) & 1); CP_COMMIT(); }

        uint32_t st = sb + (ch & 1) * STG_SZ;
        #pragma unroll
        for (int ks = 0; ks < 2; ks++) {
            uint32_t a_h[2][4], a_l[2][4];
            #pragma unroll
            for (int mt = 0; mt < 2; mt++) {
                uint32_t off = (uint32_t)((wm * 32 + mt * 16 + (lane & 15)) * RS2
                                          + (ks * 16 + ((lane >> 4) << 3)) * 2);
                ldm_x4(a_h[mt][0], a_h[mt][1], a_h[mt][2], a_h[mt][3], st + off);
                ldm_x4(a_l[mt][0], a_l[mt][1], a_l[mt][2], a_l[mt][3], st + 10240 + off);
            }
            #pragma unroll
            for (int ng = 0; ng < 4; ng++) {
                uint32_t b_h[2][2], b_l[2][2];
                uint32_t off = (uint32_t)((wn * 64 + ng * 16 + ((lane & 16) >> 1) + (lane & 7)) * RS2
                                          + (ks * 16 + (lane & 8)) * 2);
                ldm_x4(b_h[0][0], b_h[0][1], b_h[1][0], b_h[1][1], st + 20480 + off);
                ldm_x4(b_l[0][0], b_l[0][1], b_l[1][0], b_l[1][1], st + 30720 + off);
                #pragma unroll
                for (int mt = 0; mt < 2; mt++) {
                    #pragma unroll
                    for (int sub = 0; sub < 2; sub++) {
                        float* a = acc[mt][ng * 2 + sub];
                        mma_bf16(a, a_h[mt], b_h[sub]);
                        mma_bf16(a, a_h[mt], b_l[sub]);
                        mma_bf16(a, a_l[mt], b_h[sub]);
                    }
                }
            }
        }
        __syncthreads();
    }

    int g = lane >> 2, q = lane & 3;
    #pragma unroll
    for (int mt = 0; mt < 2; mt++) {
        int m0 = row0 + wm * 32 + mt * 16 + g;
        #pragma unroll
        for (int nt = 0; nt < 8; nt++) {
            int n = col0 + wn * 64 + nt * 8 + q * 2;
            float b0 = bias[n], b1 = bias[n + 1];
            float v00 = gelu_exact(acc[mt][nt][0] + b0), v01 = gelu_exact(acc[mt][nt][1] + b1);
            float v10 = gelu_exact(acc[mt][nt][2] + b0), v11 = gelu_exact(acc[mt][nt][3] + b1);
            __nv_bfloat16 h0, l0, h1, l1;
            split_bf16(v00, h0, l0); split_bf16(v01, h1, l1);
            *(__nv_bfloat162*)(outH + (size_t)m0 * N + n) = __nv_bfloat162(h0, h1);
            *(__nv_bfloat162*)(outL + (size_t)m0 * N + n) = __nv_bfloat162(l0, l1);
            split_bf16(v10, h0, l0); split_bf16(v11, h1, l1);
            *(__nv_bfloat162*)(outH + (size_t)(m0 + 8) * N + n) = __nv_bfloat162(h0, h1);
            *(__nv_bfloat162*)(outL + (size_t)(m0 + 8) * N + n) = __nv_bfloat162(l0, l1);
        }
    }
}

// ======================= wide GEMM 64x256 with fused LN epilogue ====================
#define W_STG 51200
#define W_TOTAL 102400
#define OFF_Y 0
#define OFF_RS 69632
#define OFF_RQ 71680
#define OFF_MU 73728
#define OFF_IV 74240
#define OFF_BIAS 74752
#define OFF_LG 75776
#define OFF_LB 76800
#define OFF_WT 77824
#define OFF_BW 98624

template <int MODE2>
__global__ void __launch_bounds__(256, 2) k_mma_w(
    const __nv_bfloat16* __restrict__ Ah, const __nv_bfloat16* __restrict__ Al,
    const __nv_bfloat16* __restrict__ Bh, const __nv_bfloat16* __restrict__ Bl,
    const float* __restrict__ bias, const float* __restrict__ lng,
    const float* __restrict__ lnb, const float* __restrict__ ww,
    const float* __restrict__ bw,
    __nv_bfloat16* __restrict__ outH, __nv_bfloat16* __restrict__ outL,
    float* __restrict__ outW, int K) {
    extern __shared__ __align__(16) char smem[];
    uint32_t sb = smem_to_u32(smem);
    int t = threadIdx.x, lane = t & 31, wid = t >> 5;
    int wm = wid & 1, wn = wid >> 1;
    int row0 = blockIdx.x * 64;

    float acc[2][8][4] = {};
    const int nch = K / 32;

    auto load_stage = [&](int ch, int s) {
        int kk = ch * 32;
        uint32_t sbase = sb + s * W_STG;
        #pragma unroll
        for (int i = 0; i < 2; i++) {
            int idx = t + i * 256;
            int arr = idx >> 8;
            int rem = idx & 255;
            int row = rem >> 2, seg = rem & 3;
            const __nv_bfloat16* src = arr ? Al : Ah;
            size_t g = (size_t)(row0 + row) * K + kk + seg * 8;
            cp16(sbase + arr * 5120 + row * RS2 + seg * 16, src + g);
        }
        #pragma unroll
        for (int i = 0; i < 8; i++) {
            int idx = t + i * 256;
            int arr = idx >> 10;
            int rem = idx & 1023;
            int row = rem >> 2, seg = rem & 3;
            const __nv_bfloat16* src = arr ? Bl : Bh;
            size_t g = (size_t)row * K + kk + seg * 8;
            cp16(sbase + 10240 + arr * 20480 + row * RS2 + seg * 16, src + g);
        }
    };

    load_stage(0, 0);
    CP_COMMIT();

    for (int ch = 0; ch < nch; ch++) {
        CP_WAIT0();
        __syncthreads();
        if (ch + 1 < nch) { load_stage(ch + 1, (ch + 1) & 1); CP_COMMIT(); }

        uint32_t st = sb + (ch & 1) * W_STG;
        #pragma unroll
        for (int ks = 0; ks < 2; ks++) {
            uint32_t a_h[2][4], a_l[2][4];
            #pragma unroll
            for (int mt = 0; mt < 2; mt++) {
                uint32_t off = (uint32_t)((wm * 32 + mt * 16 + (lane & 15)) * RS2
                                          + (ks * 16 + ((lane >> 4) << 3)) * 2);
                ldm_x4(a_h[mt][0], a_h[mt][1], a_h[mt][2], a_h[mt][3], st + off);
                ldm_x4(a_l[mt][0], a_l[mt][1], a_l[mt][2], a_l[mt][3], st + 5120 + off);
            }
            #pragma unroll
            for (int ng = 0; ng < 4; ng++) {
                uint32_t b_h[2][2], b_l[2][2];
                uint32_t off = (uint32_t)((wn * 64 + ng * 16 + ((lane & 16) >> 1) + (lane & 7)) * RS2
                                          + (ks * 16 + (lane & 8)) * 2);
                ldm_x4(b_h[0][0], b_h[0][1], b_h[1][0], b_h[1][1], st + 10240 + off);
                ldm_x4(b_l[0][0], b_l[0][1], b_l[1][0], b_l[1][1], st + 30720 + off);
                #pragma unroll
                for (int mt = 0; mt < 2; mt++) {
                    #pragma unroll
                    for (int sub = 0; sub < 2; sub++) {
                        float* a = acc[mt][ng * 2 + sub];
                        mma_bf16(a, a_h[mt], b_h[sub]);
                        mma_bf16(a, a_h[mt], b_l[sub]);
                        mma_bf16(a, a_l[mt], b_h[sub]);
                    }
                }
            }
        }
        __syncthreads();
    }

    // ---------------- fused epilogue ----------------
    int g = lane >> 2, q = lane & 3;
    float* bias_s = (float*)(smem + OFF_BIAS);
    float* g_s = (float*)(smem + OFF_LG);
    float* b_s = (float*)(smem + OFF_LB);
    float* redS = (float*)(smem + OFF_RS);
    float* redQ = (float*)(smem + OFF_RQ);
    float* mu_s = (float*)(smem + OFF_MU);
    float* iv_s = (float*)(smem + OFF_IV);

    bias_s[t] = bias[t];
    g_s[t] = lng[t];
    b_s[t] = lnb[t];
    if (MODE2 == 1) {
        float* wt = (float*)(smem + OFF_WT);
        for (int idx = t; idx < HIDN * NVAR; idx += 256) {
            int c = idx / NVAR, j = idx % NVAR;
            wt[j * 260 + c] = ww[idx];
        }
        if (t < NVAR) ((float*)(smem + OFF_BW))[t] = bw[t];
    }
    __syncthreads();

    #pragma unroll
    for (int mt = 0; mt < 2; mt++) {
        #pragma unroll
        for (int nt = 0; nt < 8; nt++) {
            int c0 = wn * 64 + nt * 8 + q * 2;
            acc[mt][nt][0] += bias_s[c0];     acc[mt][nt][1] += bias_s[c0 + 1];
            acc[mt][nt][2] += bias_s[c0];     acc[mt][nt][3] += bias_s[c0 + 1];
        }
    }

    #pragma unroll
    for (int mt = 0; mt < 2; mt++) {
        #pragma unroll
        for (int rr = 0; rr < 2; rr++) {
            float s = 0.f;
            #pragma unroll
            for (int nt = 0; nt < 8; nt++) s += acc[mt][nt][rr * 2] + acc[mt][nt][rr * 2 + 1];
            s += __shfl_xor_sync(0xffffffffu, s, 1);
            s += __shfl_xor_sync(0xffffffffu, s, 2);
            int r = wm * 32 + mt * 16 + rr * 8 + g;
            if (q == 0) redS[r * 8 + wn] = s;
        }
    }
    __syncthreads();
    if (t < 64) mu_s[t] = (redS[t * 8] + redS[t * 8 + 1] + redS[t * 8 + 2] + redS[t * 8 + 3]) * (1.f / 256.f);
    __syncthreads();

    #pragma unroll
    for (int mt = 0; mt < 2; mt++) {
        #pragma unroll
        for (int rr = 0; rr < 2; rr++) {
            int r = wm * 32 + mt * 16 + rr * 8 + g;
            float mu = mu_s[r];
            float s = 0.f;
            #pragma unroll
            for (int nt = 0; nt < 8; nt++) {
                float d0 = acc[mt][nt][rr * 2] - mu, d1 = acc[mt][nt][rr * 2 + 1] - mu;
                s += d0 * d0 + d1 * d1;
            }
            s += __shfl_xor_sync(0xffffffffu, s, 1);
            s += __shfl_xor_sync(0xffffffffu, s, 2);
            if (q == 0) redQ[r * 8 + wn] = s;
        }
    }
    __syncthreads();
    if (t < 64) iv_s[t] = rsqrtf((redQ[t * 8] + redQ[t * 8 + 1] + redQ[t * 8 + 2] + redQ[t * 8 + 3]) * (1.f / 256.f) + LN_EPS);
    __syncthreads();

    #pragma unroll
    for (int mt = 0; mt < 2; mt++) {
        #pragma unroll
        for (int rr = 0; rr < 2; rr++) {
            int r = wm * 32 + mt * 16 + rr * 8 + g;
            float mu = mu_s[r], iv = iv_s[r];
            int grow = row0 + r;
            #pragma unroll
            for (int nt = 0; nt < 8; nt++) {
                int c0 = wn * 64 + nt * 8 + q * 2;
                float y0 = (acc[mt][nt][rr * 2] - mu) * iv * g_s[c0] + b_s[c0];
                float y1 = (acc[mt][nt][rr * 2 + 1] - mu) * iv * g_s[c0 + 1] + b_s[c0 + 1];
                if (MODE2 == 0) {
                    __nv_bfloat16 h0, l0, h1, l1;
                    split_bf16(y0, h0, l0); split_bf16(y1, h1, l1);
                    *(__nv_bfloat162*)(outH + (size_t)grow * HIDN + c0) = __nv_bfloat162(h0, h1);
                    *(__nv_bfloat162*)(outL + (size_t)grow * HIDN + c0) = __nv_bfloat162(l0, l1);
                } else {
                    *(float2*)(smem + OFF_Y + (r * 264 + c0) * 4) = make_float2(y0, y1);
                }
            }
        }
    }

    if (MODE2 == 1) {
        __syncthreads();
        float* Y = (float*)(smem + OFF_Y);
        float* wt = (float*)(smem + OFF_WT);
        float* bw_s = (float*)(smem + OFF_BW);
        const size_t WOFF = (size_t)MTOK * HIDN;
        #pragma unroll
        for (int rr2 = 0; rr2 < 8; rr2++) {
            int r = wid * 8 + rr2;
            int m = row0 + r;
            float yv[8];
            #pragma unroll
            for (int i = 0; i < 8; i++) yv[i] = Y[r * 264 + lane + 32 * i];
            float lg[NVAR];
            #pragma unroll
            for (int j = 0; j < NVAR; j++) {
                float s = 0.f;
                #pragma unroll
                for (int i = 0; i < 8; i++) s += yv[i] * wt[j * 260 + lane + 32 * i];
                lg[j] = s;
            }
            #pragma unroll
            for (int j = 0; j < NVAR; j++) {
                #pragma unroll
                for (int o = 16; o > 0; o >>= 1) lg[j] += __shfl_xor_sync(0xffffffffu, lg[j], o);
                lg[j] += bw_s[j];
            }
            float mx = -1e30f;
            #pragma unroll
            for (int j = 0; j < NVAR; j++) mx = fmaxf(mx, lg[j]);
            float sum = 0.f;
            #pragma unroll
            for (int j = 0; j < NVAR; j++) { lg[j] = __expf(lg[j] - mx); sum += lg[j]; }
            float invs = 1.0f / sum;
            float myw = 0.f;
            #pragma unroll
            for (int j = 0; j < NVAR; j++) if (lane == j) myw = lg[j] * invs;
            if (lane < NVAR) outW[WOFF + (size_t)m * NVAR + lane] = myw;
        }
    }
}

// ======================= K_final: weights + x -> vs_output (float4) ==============
__global__ void k_final(const float* __restrict__ x, float* __restrict__ out) {
    int t = threadIdx.x;
    int warp = t >> 5, lane = t & 31;
    const size_t WOFF = (size_t)MTOK * HIDN;
    #pragma unroll
    for (int tk = 0; tk < 2; tk++) {
        int m = blockIdx.x * 16 + warp * 2 + tk;
        float lg[NVAR];
        #pragma unroll
        for (int j = 0; j < NVAR; j++) lg[j] = out[WOFF + (size_t)m * NVAR + j];
        const float* xb = x + (size_t)m * (NVAR * HIDN);
        int c0 = lane * 8;
        float a[8] = {};
        #pragma unroll 4
        for (int vv = 0; vv < NVAR; vv++) {
            float wv = lg[vv];
            float4 p0 = *(const float4*)(xb + vv * HIDN + c0);
            float4 p1 = *(const float4*)(xb + vv * HIDN + c0 + 4);
            a[0] += wv * p0.x; a[1] += wv * p0.y; a[2] += wv * p0.z; a[3] += wv * p0.w;
            a[4] += wv * p1.x; a[5] += wv * p1.y; a[6] += wv * p1.z; a[7] += wv * p1.w;
        }
        *(float4*)(out + (size_t)m * HIDN + c0) = make_float4(a[0], a[1], a[2], a[3]);
        *(float4*)(out + (size_t)m * HIDN + c0 + 4) = make_float4(a[4], a[5], a[6], a[7]);
    }
}

extern "C" void kernel_launch(void* const* d_in, const int* in_sizes, int n_in,
                              void* d_out, int out_size) {
    (void)in_sizes; (void)n_in; (void)out_size;
    const float* x     = (const float*)d_in[0];
    const float* cls   = (const float*)d_in[1];
    const float* wq    = (const float*)d_in[2];
    const float* bq    = (const float*)d_in[3];
    const float* wk    = (const float*)d_in[4];
    const float* bk    = (const float*)d_in[5];
    const float* wv    = (const float*)d_in[6];
    const float* bv    = (const float*)d_in[7];
    const float* wo    = (const float*)d_in[8];
    const float* bo    = (const float*)d_in[9];
    const float* ln1_g = (const float*)d_in[10];
    const float* ln1_b = (const float*)d_in[11];
    const float* w1    = (const float*)d_in[12];
    const float* b1    = (const float*)d_in[13];
    const float* w2    = (const float*)d_in[14];
    const float* b2    = (const float*)d_in[15];
    const float* ln2_g = (const float*)d_in[16];
    const float* ln2_b = (const float*)d_in[17];
    const float* ww    = (const float*)d_in[18];
    const float* bw    = (const float*)d_in[19];
    float* out = (float*)d_out;

    cudaFuncSetAttribute(k_mma_ff1, cudaFuncAttributeMaxDynamicSharedMemorySize, MM_TOTAL2);
    cudaFuncSetAttribute(k_mma_ctx, cudaFuncAttributeMaxDynamicSharedMemorySize, CT_TOTAL);
    cudaFuncSetAttribute(k_mma_w<0>, cudaFuncAttributeMaxDynamicSharedMemorySize, W_TOTAL);
    cudaFuncSetAttribute(k_mma_w<1>, cudaFuncAttributeMaxDynamicSharedMemorySize, W_TOTAL);

    void *p_ctxh, *p_ctxl, *p_h1h, *p_h1l, *p_h2h, *p_h2l, *p_cbias;
    void *p_woh, *p_wol, *p_w1h, *p_w1l, *p_w2h, *p_w2l;
    cudaGetSymbolAddress(&p_ctxh, g_ctxh);  cudaGetSymbolAddress(&p_ctxl, g_ctxl);
    cudaGetSymbolAddress(&p_h1h, g_h1h);    cudaGetSymbolAddress(&p_h1l, g_h1l);
    cudaGetSymbolAddress(&p_h2h, g_h2h);    cudaGetSymbolAddress(&p_h2l, g_h2l);
    cudaGetSymbolAddress(&p_cbias, g_cbias);
    cudaGetSymbolAddress(&p_woh, g_woT_h);  cudaGetSymbolAddress(&p_wol, g_woT_l);
    cudaGetSymbolAddress(&p_w1h, g_w1T_h);  cudaGetSymbolAddress(&p_w1l, g_w1T_l);
    cudaGetSymbolAddress(&p_w2h, g_w2T_h);  cudaGetSymbolAddress(&p_w2l, g_w2T_l);

    k_pre<<<1, 256>>>(cls, wq, bq, wk, bk, wo, bo, bv);
    k_wsplit_all<<<dim3(32, 4), 256>>>(wo, w1, w2, wv);   // 32 tiles covers largest (8x32=256... w1: 8x32=256 tiles? no: FFD/32*HIDN/32 = 32*8 = 256/8=32? tiles_k*tiles_n = 8*32 = 256 -> need 256)
    // correction: use 256 blocks to cover all tile counts
    // (w1/w2 have 8*32 = 256 tiles; wo/wv have 64; extra blocks early-exit)
    k_wsplit_all<<<dim3(256, 4), 256>>>(wo, w1, w2, wv);

    k1_attn<<<MTOK, 256>>>(x);
    k_mma_ctx<<<dim3(MTOK / 128, NHEAD), 256, CT_TOTAL>>>();

    // o-proj + cbias + LN1 -> h1 hi/lo   (K=256, N=256)
    k_mma_w<0><<<MTOK / 64, 256, W_TOTAL>>>(
        (const __nv_bfloat16*)p_ctxh, (const __nv_bfloat16*)p_ctxl,
        (const __nv_bfloat16*)p_woh, (const __nv_bfloat16*)p_wol,
        (const float*)p_cbias, ln1_g, ln1_b, nullptr, nullptr,
        (__nv_bfloat16*)p_h1h, (__nv_bfloat16*)p_h1l, nullptr, HIDN);

    // FF1: h2 = gelu(h1 @ w1 + b1)    (K=256, N=1024)
    k_mma_ff1<<<dim3(FFD / 128, MTOK / 128), 256, MM_TOTAL2>>>(
        (const __nv_bfloat16*)p_h1h, (const __nv_bfloat16*)p_h1l,
        (const __nv_bfloat16*)p_w1h, (const __nv_bfloat16*)p_w1l,
        b1, (__nv_bfloat16*)p_h2h, (__nv_bfloat16*)p_h2l, HIDN, FFD);

    // FF2 + b2 + LN2 + logits + softmax -> weights   (K=1024, N=256)
    k_mma_w<1><<<MTOK / 64, 256, W_TOTAL>>>(
        (const __nv_bfloat16*)p_h2h, (const __nv_bfloat16*)p_h2l,
        (const __nv_bfloat16*)p_w2h, (const __nv_bfloat16*)p_w2l,
        b2, ln2_g, ln2_b, ww, bw, nullptr, nullptr, out, FFD);

    k_final<<<MTOK / 16, 256>>>(x, out);
}

// round 17
// speedup vs baseline: 1.1771x; 1.0554x over previous
#include <cuda_runtime.h>
#include <cuda_bf16.h>
#include <math.h>
#include <cstdint>

#define HIDN 256
#define NVAR 20
#define NHEAD 8
#define DHEAD 32
#define MTOK 16384          // B*T
#define FFD 1024
#define ATT_SCALE 0.17677669529663687f
#define LN_EPS 1e-5f

// ======================= helpers =======================
__device__ __forceinline__ uint32_t smem_to_u32(const void* p) {
    uint32_t a;
    asm("{ .reg .u64 t; cvta.to.shared.u64 t, %1; cvt.u32.u64 %0, t; }" : "=r"(a) : "l"(p));
    return a;
}
__device__ __forceinline__ void ldm_x4(uint32_t& r0, uint32_t& r1, uint32_t& r2, uint32_t& r3,
                                       uint32_t addr) {
    asm volatile("ldmatrix.sync.aligned.m8n8.x4.shared.b16 {%0,%1,%2,%3}, [%4];"
                 : "=r"(r0), "=r"(r1), "=r"(r2), "=r"(r3) : "r"(addr));
}
__device__ __forceinline__ void mma_bf16(float* c, const uint32_t* a, const uint32_t* b) {
    asm volatile(
        "mma.sync.aligned.m16n8k16.row.col.f32.bf16.bf16.f32 "
        "{%0,%1,%2,%3}, {%4,%5,%6,%7}, {%8,%9}, {%0,%1,%2,%3};"
        : "+f"(c[0]), "+f"(c[1]), "+f"(c[2]), "+f"(c[3])
        : "r"(a[0]), "r"(a[1]), "r"(a[2]), "r"(a[3]), "r"(b[0]), "r"(b[1]));
}
__device__ __forceinline__ void cp16(uint32_t dst, const void* src) {
    asm volatile("cp.async.cg.shared.global [%0], [%1], 16;" :: "r"(dst), "l"(src));
}
#define CP_COMMIT() asm volatile("cp.async.commit_group;" ::: "memory")
#define CP_WAIT0()  asm volatile("cp.async.wait_group 0;" ::: "memory")
__device__ __forceinline__ void split_bf16(float v, __nv_bfloat16& h, __nv_bfloat16& l) {
    h = __float2bfloat16(v);
    l = __float2bfloat16(v - __bfloat162float(h));
}
__device__ __forceinline__ float gelu_exact(float v) {
    return 0.5f * v * (1.0f + erff(v * 0.70710678118654752f));
}

// ======================= scratch =======================
__device__ __align__(256) float g_S[NHEAD * HIDN];
__device__ __align__(256) float g_sbias[NHEAD];
__device__ __align__(256) float g_cbias[HIDN];
__device__ __align__(256) __nv_bfloat16 g_xwh[(size_t)MTOK * 2048];
__device__ __align__(256) __nv_bfloat16 g_xwl[(size_t)MTOK * 2048];
__device__ __align__(256) __nv_bfloat16 g_ctxh[(size_t)MTOK * HIDN];
__device__ __align__(256) __nv_bfloat16 g_ctxl[(size_t)MTOK * HIDN];
__device__ __align__(256) __nv_bfloat16 g_h1h[(size_t)MTOK * HIDN];
__device__ __align__(256) __nv_bfloat16 g_h1l[(size_t)MTOK * HIDN];
__device__ __align__(256) __nv_bfloat16 g_h2h[(size_t)MTOK * FFD];
__device__ __align__(256) __nv_bfloat16 g_h2l[(size_t)MTOK * FFD];
__device__ __align__(256) __nv_bfloat16 g_woT_h[HIDN * HIDN], g_woT_l[HIDN * HIDN];
__device__ __align__(256) __nv_bfloat16 g_w1T_h[FFD * HIDN],  g_w1T_l[FFD * HIDN];
__device__ __align__(256) __nv_bfloat16 g_w2T_h[HIDN * FFD],  g_w2T_l[HIDN * FFD];
__device__ __align__(256) __nv_bfloat16 g_wvT_h[HIDN * HIDN], g_wvT_l[HIDN * HIDN];

// ======================= K0: tiny precompute =======================
__global__ void k_pre(const float* __restrict__ cls, const float* __restrict__ wq,
                      const float* __restrict__ bq, const float* __restrict__ wk,
                      const float* __restrict__ bk, const float* __restrict__ wo,
                      const float* __restrict__ bo, const float* __restrict__ bv) {
    __shared__ float q_s[HIDN];
    int t = threadIdx.x;
    float acc = bq[t];
    for (int c = 0; c < HIDN; c++) acc += cls[c] * wq[c * HIDN + t];
    q_s[t] = acc;
    __syncthreads();
    for (int idx = t; idx < NHEAD * HIDN; idx += 256) {
        int h = idx >> 8, c = idx & 255;
        float s = 0.f;
        #pragma unroll 8
        for (int d = 0; d < DHEAD; d++) s += wk[c * HIDN + h * DHEAD + d] * q_s[h * DHEAD + d];
        g_S[idx] = s;
    }
    if (t < NHEAD) {
        float s = 0.f;
        for (int d = 0; d < DHEAD; d++) s += bk[t * DHEAD + d] * q_s[t * DHEAD + d];
        g_sbias[t] = s;
    }
    float cb = bo[t];
    for (int c = 0; c < HIDN; c++) cb += bv[c] * wo[c * HIDN + t];
    g_cbias[t] = cb;
}

// ======================= tiled weight transpose+split (coalesced) =======================
__global__ void k_wsplit_all(const float* __restrict__ wo, const float* __restrict__ w1,
                             const float* __restrict__ w2, const float* __restrict__ wv) {
    int which = blockIdx.y;
    const float* w;
    __nv_bfloat16 *hi, *lo;
    int K, N;
    if (which == 0)      { w = wo; hi = g_woT_h; lo = g_woT_l; K = HIDN; N = HIDN; }
    else if (which == 1) { w = w1; hi = g_w1T_h; lo = g_w1T_l; K = HIDN; N = FFD; }
    else if (which == 2) { w = w2; hi = g_w2T_h; lo = g_w2T_l; K = FFD;  N = HIDN; }
    else                 { w = wv; hi = g_wvT_h; lo = g_wvT_l; K = HIDN; N = HIDN; }
    int tiles_n = N >> 5, tiles_k = K >> 5;
    int tile = blockIdx.x;
    if (tile >= tiles_n * tiles_k) return;
    int tk = tile / tiles_n, tn = tile % tiles_n;
    __shared__ float s[32][33];
    int t = threadIdx.x;
    #pragma unroll
    for (int i = 0; i < 4; i++) {
        int e = t + i * 256;
        int row = e >> 5, col = e & 31;
        s[row][col] = w[(size_t)(tk * 32 + row) * N + tn * 32 + col];
    }
    __syncthreads();
    #pragma unroll
    for (int i = 0; i < 4; i++) {
        int e = t + i * 256;
        int row = e >> 5, col = e & 31;
        __nv_bfloat16 h, l;
        split_bf16(s[col][row], h, l);
        size_t o = (size_t)(tn * 32 + row) * K + tk * 32 + col;
        hi[o] = h;
        lo[o] = l;
    }
}

// ======================= K1: fused attention -> xw hi/lo (2-pass S, 4 blk/SM) =====
#define XROW 260
__global__ void __launch_bounds__(256, 4) k1_attn(const float* __restrict__ x) {
    __shared__ float x_s[NVAR * XROW];
    __shared__ float sc_s[NHEAD * NVAR];
    __shared__ float attn_s[NVAR * NHEAD];
    int m = blockIdx.x;
    int t = threadIdx.x, lane = t & 31, w = t >> 5;
    const float* xb = x + (size_t)m * (NVAR * HIDN);

    #pragma unroll
    for (int i = 0; i < 5; i++) {
        int e4 = t + i * 256;
        float4 val = *(const float4*)(xb + e4 * 4);
        int e = e4 * 4;
        int v = e >> 8, c = e & 255;
        *(float4*)&x_s[v * XROW + c] = val;
    }
    __syncthreads();

    // scores: two passes of 4 heads each; s_r is 32 regs, reused across passes
    #pragma unroll 1
    for (int hp = 0; hp < 2; hp++) {
        float s_r[4][8];
        #pragma unroll
        for (int hh = 0; hh < 4; hh++) {
            const float* sp = &g_S[(hp * 4 + hh) * 256 + lane * 8];
            float4 s0 = *(const float4*)sp;
            float4 s1 = *(const float4*)(sp + 4);
            s_r[hh][0] = s0.x; s_r[hh][1] = s0.y; s_r[hh][2] = s0.z; s_r[hh][3] = s0.w;
            s_r[hh][4] = s1.x; s_r[hh][5] = s1.y; s_r[hh][6] = s1.z; s_r[hh][7] = s1.w;
        }
        for (int v = w; v < NVAR; v += 8) {
            float4 xa = *(const float4*)&x_s[v * XROW + lane * 8];
            float4 xc = *(const float4*)&x_s[v * XROW + lane * 8 + 4];
            float xr[8] = {xa.x, xa.y, xa.z, xa.w, xc.x, xc.y, xc.z, xc.w};
            float sums[4];
            #pragma unroll
            for (int hh = 0; hh < 4; hh++) {
                float s = 0.f;
                #pragma unroll
                for (int i = 0; i < 8; i++) s += xr[i] * s_r[hh][i];
                sums[hh] = s;
            }
            #pragma unroll
            for (int hh = 0; hh < 4; hh++) {
                #pragma unroll
                for (int o = 16; o > 0; o >>= 1)
                    sums[hh] += __shfl_xor_sync(0xffffffffu, sums[hh], o);
            }
            if (lane == 0) {
                #pragma unroll
                for (int hh = 0; hh < 4; hh++) {
                    int h = hp * 4 + hh;
                    sc_s[h * NVAR + v] = (sums[hh] + g_sbias[h]) * ATT_SCALE;
                }
            }
        }
    }
    __syncthreads();

    {
        float my = (lane < NVAR) ? sc_s[w * NVAR + lane] : -1e30f;
        float mx = my;
        #pragma unroll
        for (int o = 16; o > 0; o >>= 1) mx = fmaxf(mx, __shfl_xor_sync(0xffffffffu, mx, o));
        float e = (lane < NVAR) ? __expf(my - mx) : 0.f;
        float s = e;
        #pragma unroll
        for (int o = 16; o > 0; o >>= 1) s += __shfl_xor_sync(0xffffffffu, s, o);
        if (lane < NVAR) attn_s[lane * 8 + w] = e / s;
    }
    __syncthreads();

    float acc[NHEAD] = {};
    #pragma unroll 4
    for (int v = 0; v < NVAR; v++) {
        float xv = x_s[v * XROW + t];
        float4 a0 = *(const float4*)&attn_s[v * 8];
        float4 a1 = *(const float4*)&attn_s[v * 8 + 4];
        acc[0] += a0.x * xv; acc[1] += a0.y * xv; acc[2] += a0.z * xv; acc[3] += a0.w * xv;
        acc[4] += a1.x * xv; acc[5] += a1.y * xv; acc[6] += a1.z * xv; acc[7] += a1.w * xv;
    }
    size_t base = (size_t)m * 2048;
    #pragma unroll
    for (int j = 0; j < NHEAD; j++) {
        __nv_bfloat16 hh, ll;
        split_bf16(acc[j], hh, ll);
        g_xwh[base + j * 256 + t] = hh;
        g_xwl[base + j * 256 + t] = ll;
    }
}

// ======================= per-head ctx MMA GEMM (KC=32, 2-stage, 4 blk/SM) ==========
#define CRS 80
#define CT_STG 25600
#define CT_TOTAL (2 * CT_STG)
__global__ void __launch_bounds__(256, 4) k_mma_ctx() {
    extern __shared__ __align__(16) char smem[];
    uint32_t sb = smem_to_u32(smem);
    int t = threadIdx.x, lane = t & 31, wid = t >> 5;
    int row0 = blockIdx.x * 128, h = blockIdx.y;

    float acc[4][4] = {};

    auto load_stage = [&](int ch, int s) {
        int kk = ch * 32;
        uint32_t base = sb + s * CT_STG;
        #pragma unroll
        for (int i = 0; i < 4; i++) {
            int idx = t + i * 256;
            int arr = idx >> 9;
            int rem = idx & 511;
            int row = rem >> 2, seg = rem & 3;
            const __nv_bfloat16* src = arr ? g_xwl : g_xwh;
            size_t gidx = (size_t)(row0 + row) * 2048 + h * 256 + kk + seg * 8;
            cp16(base + arr * 10240 + row * CRS + seg * 16, src + gidx);
        }
        {
            int arr = t >> 7;
            int rem = t & 127;
            int row = rem >> 2, seg = rem & 3;
            const __nv_bfloat16* src = arr ? g_wvT_l : g_wvT_h;
            size_t gidx = (size_t)(h * 32 + row) * HIDN + kk + seg * 8;
            cp16(base + 20480 + arr * 2560 + row * CRS + seg * 16, src + gidx);
        }
    };

    load_stage(0, 0);
    CP_COMMIT();

    for (int ch = 0; ch < 8; ch++) {
        CP_WAIT0();
        __syncthreads();
        if (ch + 1 < 8) { load_stage(ch + 1, (ch + 1) & 1); CP_COMMIT(); }

        uint32_t st = sb + (ch & 1) * CT_STG;
        #pragma unroll
        for (int ks = 0; ks < 2; ks++) {
            uint32_t a_h[4], a_l[4], b_h[4][2], b_l[4][2];
            uint32_t aoff = (uint32_t)((wid * 16 + (lane & 15)) * CRS
                                       + (ks * 16 + ((lane >> 4) << 3)) * 2);
            ldm_x4(a_h[0], a_h[1], a_h[2], a_h[3], st + aoff);
            ldm_x4(a_l[0], a_l[1], a_l[2], a_l[3], st + 10240 + aoff);
            #pragma unroll
            for (int ng = 0; ng < 2; ng++) {
                uint32_t boff = (uint32_t)((ng * 16 + ((lane & 16) >> 1) + (lane & 7)) * CRS
                                           + (ks * 16 + (lane & 8)) * 2);
                ldm_x4(b_h[2 * ng][0], b_h[2 * ng][1], b_h[2 * ng + 1][0], b_h[2 * ng + 1][1],
                       st + 20480 + boff);
                ldm_x4(b_l[2 * ng][0], b_l[2 * ng][1], b_l[2 * ng + 1][0], b_l[2 * ng + 1][1],
                       st + 23040 + boff);
            }
            #pragma unroll
            for (int nt = 0; nt < 4; nt++) {
                mma_bf16(acc[nt], a_h, b_h[nt]);
                mma_bf16(acc[nt], a_h, b_l[nt]);
                mma_bf16(acc[nt], a_l, b_h[nt]);
            }
        }
        __syncthreads();
    }

    int g = lane >> 2, q = lane & 3;
    int m0 = row0 + wid * 16 + g;
    #pragma unroll
    for (int nt = 0; nt < 4; nt++) {
        int n = h * 32 + nt * 8 + q * 2;
        __nv_bfloat16 h0, l0, h1, l1;
        split_bf16(acc[nt][0], h0, l0); split_bf16(acc[nt][1], h1, l1);
        *(__nv_bfloat162*)(g_ctxh + (size_t)m0 * HIDN + n) = __nv_bfloat162(h0, h1);
        *(__nv_bfloat162*)(g_ctxl + (size_t)m0 * HIDN + n) = __nv_bfloat162(l0, l1);
        split_bf16(acc[nt][2], h0, l0); split_bf16(acc[nt][3], h1, l1);
        *(__nv_bfloat162*)(g_ctxh + (size_t)(m0 + 8) * HIDN + n) = __nv_bfloat162(h0, h1);
        *(__nv_bfloat162*)(g_ctxl + (size_t)(m0 + 8) * HIDN + n) = __nv_bfloat162(l0, l1);
    }
}

// ======================= FF1 GEMM 128x128 (cp.async 2-stage) ===============
#define KC2 32
#define RS2 80
#define STG_SZ 40960
#define MM_TOTAL2 (2 * STG_SZ)

__global__ void __launch_bounds__(256, 2) k_mma_ff1(
    const __nv_bfloat16* __restrict__ Ah, const __nv_bfloat16* __restrict__ Al,
    const __nv_bfloat16* __restrict__ Bh, const __nv_bfloat16* __restrict__ Bl,
    const float* __restrict__ bias,
    __nv_bfloat16* __restrict__ outH, __nv_bfloat16* __restrict__ outL,
    int K, int N) {
    extern __shared__ __align__(16) char smem[];
    uint32_t sb = smem_to_u32(smem);
    int t = threadIdx.x, lane = t & 31, wid = t >> 5;
    int wm = wid & 3, wn = wid >> 2;
    int row0 = blockIdx.y * 128, col0 = blockIdx.x * 128;

    float acc[2][8][4] = {};
    const int nch = K / KC2;

    auto load_stage = [&](int ch, int s) {
        int kk = ch * KC2;
        uint32_t sbase = sb + s * STG_SZ;
        #pragma unroll
        for (int i = 0; i < 8; i++) {
            int idx = t + i * 256;
            int arr = idx >> 9;
            int rem = idx & 511;
            int row = rem >> 2, seg = rem & 3;
            const __nv_bfloat16* src = (arr == 0) ? Ah : (arr == 1) ? Al : (arr == 2) ? Bh : Bl;
            size_t g = (size_t)(((arr < 2) ? row0 : col0) + row) * K + kk + seg * 8;
            cp16(sbase + arr * 10240 + row * RS2 + seg * 16, src + g);
        }
    };

    load_stage(0, 0);
    CP_COMMIT();

    for (int ch = 0; ch < nch; ch++) {
        CP_WAIT0();
        __syncthreads();
        if (ch + 1 < nch) { load_stage(ch + 1, (ch + 1) & 1); CP_COMMIT(); }

        uint32_t st = sb + (ch & 1) * STG_SZ;
        #pragma unroll
        for (int ks = 0; ks < 2; ks++) {
            uint32_t a_h[2][4], a_l[2][4];
            #pragma unroll
            for (int mt = 0; mt < 2; mt++) {
                uint32_t off = (uint32_t)((wm * 32 + mt * 16 + (lane & 15)) * RS2
                                          + (ks * 16 + ((lane >> 4) << 3)) * 2);
                ldm_x4(a_h[mt][0], a_h[mt][1], a_h[mt][2], a_h[mt][3], st + off);
                ldm_x4(a_l[mt][0], a_l[mt][1], a_l[mt][2], a_l[mt][3], st + 10240 + off);
            }
            #pragma unroll
            for (int ng = 0; ng < 4; ng++) {
                uint32_t b_h[2][2], b_l[2][2];
                uint32_t off = (uint32_t)((wn * 64 + ng * 16 + ((lane & 16) >> 1) + (lane & 7)) * RS2
                                          + (ks * 16 + (lane & 8)) * 2);
                ldm_x4(b_h[0][0], b_h[0][1], b_h[1][0], b_h[1][1], st + 20480 + off);
                ldm_x4(b_l[0][0], b_l[0][1], b_l[1][0], b_l[1][1], st + 30720 + off);
                #pragma unroll
                for (int mt = 0; mt < 2; mt++) {
                    #pragma unroll
                    for (int sub = 0; sub < 2; sub++) {
                        float* a = acc[mt][ng * 2 + sub];
                        mma_bf16(a, a_h[mt], b_h[sub]);
                        mma_bf16(a, a_h[mt], b_l[sub]);
                        mma_bf16(a, a_l[mt], b_h[sub]);
                    }
                }
            }
        }
        __syncthreads();
    }

    int g = lane >> 2, q = lane & 3;
    #pragma unroll
    for (int mt = 0; mt < 2; mt++) {
        int m0 = row0 + wm * 32 + mt * 16 + g;
        #pragma unroll
        for (int nt = 0; nt < 8; nt++) {
            int n = col0 + wn * 64 + nt * 8 + q * 2;
            float b0 = bias[n], b1 = bias[n + 1];
            float v00 = gelu_exact(acc[mt][nt][0] + b0), v01 = gelu_exact(acc[mt][nt][1] + b1);
            float v10 = gelu_exact(acc[mt][nt][2] + b0), v11 = gelu_exact(acc[mt][nt][3] + b1);
            __nv_bfloat16 h0, l0, h1, l1;
            split_bf16(v00, h0, l0); split_bf16(v01, h1, l1);
            *(__nv_bfloat162*)(outH + (size_t)m0 * N + n) = __nv_bfloat162(h0, h1);
            *(__nv_bfloat162*)(outL + (size_t)m0 * N + n) = __nv_bfloat162(l0, l1);
            split_bf16(v10, h0, l0); split_bf16(v11, h1, l1);
            *(__nv_bfloat162*)(outH + (size_t)(m0 + 8) * N + n) = __nv_bfloat162(h0, h1);
            *(__nv_bfloat162*)(outL + (size_t)(m0 + 8) * N + n) = __nv_bfloat162(l0, l1);
        }
    }
}

// ======================= wide GEMM 64x256 with fused LN epilogue ====================
#define W_STG 51200
#define W_TOTAL 102400
#define OFF_Y 0
#define OFF_RS 69632
#define OFF_RQ 71680
#define OFF_MU 73728
#define OFF_IV 74240
#define OFF_BIAS 74752
#define OFF_LG 75776
#define OFF_LB 76800
#define OFF_WT 77824
#define OFF_BW 98624

template <int MODE2>
__global__ void __launch_bounds__(256, 2) k_mma_w(
    const __nv_bfloat16* __restrict__ Ah, const __nv_bfloat16* __restrict__ Al,
    const __nv_bfloat16* __restrict__ Bh, const __nv_bfloat16* __restrict__ Bl,
    const float* __restrict__ bias, const float* __restrict__ lng,
    const float* __restrict__ lnb, const float* __restrict__ ww,
    const float* __restrict__ bw,
    __nv_bfloat16* __restrict__ outH, __nv_bfloat16* __restrict__ outL,
    float* __restrict__ outW, int K) {
    extern __shared__ __align__(16) char smem[];
    uint32_t sb = smem_to_u32(smem);
    int t = threadIdx.x, lane = t & 31, wid = t >> 5;
    int wm = wid & 1, wn = wid >> 1;
    int row0 = blockIdx.x * 64;

    float acc[2][8][4] = {};
    const int nch = K / 32;

    auto load_stage = [&](int ch, int s) {
        int kk = ch * 32;
        uint32_t sbase = sb + s * W_STG;
        #pragma unroll
        for (int i = 0; i < 2; i++) {
            int idx = t + i * 256;
            int arr = idx >> 8;
            int rem = idx & 255;
            int row = rem >> 2, seg = rem & 3;
            const __nv_bfloat16* src = arr ? Al : Ah;
            size_t g = (size_t)(row0 + row) * K + kk + seg * 8;
            cp16(sbase + arr * 5120 + row * RS2 + seg * 16, src + g);
        }
        #pragma unroll
        for (int i = 0; i < 8; i++) {
            int idx = t + i * 256;
            int arr = idx >> 10;
            int rem = idx & 1023;
            int row = rem >> 2, seg = rem & 3;
            const __nv_bfloat16* src = arr ? Bl : Bh;
            size_t g = (size_t)row * K + kk + seg * 8;
            cp16(sbase + 10240 + arr * 20480 + row * RS2 + seg * 16, src + g);
        }
    };

    load_stage(0, 0);
    CP_COMMIT();

    for (int ch = 0; ch < nch; ch++) {
        CP_WAIT0();
        __syncthreads();
        if (ch + 1 < nch) { load_stage(ch + 1, (ch + 1) & 1); CP_COMMIT(); }

        uint32_t st = sb + (ch & 1) * W_STG;
        #pragma unroll
        for (int ks = 0; ks < 2; ks++) {
            uint32_t a_h[2][4], a_l[2][4];
            #pragma unroll
            for (int mt = 0; mt < 2; mt++) {
                uint32_t off = (uint32_t)((wm * 32 + mt * 16 + (lane & 15)) * RS2
                                          + (ks * 16 + ((lane >> 4) << 3)) * 2);
                ldm_x4(a_h[mt][0], a_h[mt][1], a_h[mt][2], a_h[mt][3], st + off);
                ldm_x4(a_l[mt][0], a_l[mt][1], a_l[mt][2], a_l[mt][3], st + 5120 + off);
            }
            #pragma unroll
            for (int ng = 0; ng < 4; ng++) {
                uint32_t b_h[2][2], b_l[2][2];
                uint32_t off = (uint32_t)((wn * 64 + ng * 16 + ((lane & 16) >> 1) + (lane & 7)) * RS2
                                          + (ks * 16 + (lane & 8)) * 2);
                ldm_x4(b_h[0][0], b_h[0][1], b_h[1][0], b_h[1][1], st + 10240 + off);
                ldm_x4(b_l[0][0], b_l[0][1], b_l[1][0], b_l[1][1], st + 30720 + off);
                #pragma unroll
                for (int mt = 0; mt < 2; mt++) {
                    #pragma unroll
                    for (int sub = 0; sub < 2; sub++) {
                        float* a = acc[mt][ng * 2 + sub];
                        mma_bf16(a, a_h[mt], b_h[sub]);
                        mma_bf16(a, a_h[mt], b_l[sub]);
                        mma_bf16(a, a_l[mt], b_h[sub]);
                    }
                }
            }
        }
        __syncthreads();
    }

    // ---------------- fused epilogue ----------------
    int g = lane >> 2, q = lane & 3;
    float* bias_s = (float*)(smem + OFF_BIAS);
    float* g_s = (float*)(smem + OFF_LG);
    float* b_s = (float*)(smem + OFF_LB);
    float* redS = (float*)(smem + OFF_RS);
    float* redQ = (float*)(smem + OFF_RQ);
    float* mu_s = (float*)(smem + OFF_MU);
    float* iv_s = (float*)(smem + OFF_IV);

    bias_s[t] = bias[t];
    g_s[t] = lng[t];
    b_s[t] = lnb[t];
    if (MODE2 == 1) {
        float* wt = (float*)(smem + OFF_WT);
        for (int idx = t; idx < HIDN * NVAR; idx += 256) {
            int c = idx / NVAR, j = idx % NVAR;
            wt[j * 260 + c] = ww[idx];
        }
        if (t < NVAR) ((float*)(smem + OFF_BW))[t] = bw[t];
    }
    __syncthreads();

    #pragma unroll
    for (int mt = 0; mt < 2; mt++) {
        #pragma unroll
        for (int nt = 0; nt < 8; nt++) {
            int c0 = wn * 64 + nt * 8 + q * 2;
            acc[mt][nt][0] += bias_s[c0];     acc[mt][nt][1] += bias_s[c0 + 1];
            acc[mt][nt][2] += bias_s[c0];     acc[mt][nt][3] += bias_s[c0 + 1];
        }
    }

    #pragma unroll
    for (int mt = 0; mt < 2; mt++) {
        #pragma unroll
        for (int rr = 0; rr < 2; rr++) {
            float s = 0.f;
            #pragma unroll
            for (int nt = 0; nt < 8; nt++) s += acc[mt][nt][rr * 2] + acc[mt][nt][rr * 2 + 1];
            s += __shfl_xor_sync(0xffffffffu, s, 1);
            s += __shfl_xor_sync(0xffffffffu, s, 2);
            int r = wm * 32 + mt * 16 + rr * 8 + g;
            if (q == 0) redS[r * 8 + wn] = s;
        }
    }
    __syncthreads();
    if (t < 64) mu_s[t] = (redS[t * 8] + redS[t * 8 + 1] + redS[t * 8 + 2] + redS[t * 8 + 3]) * (1.f / 256.f);
    __syncthreads();

    #pragma unroll
    for (int mt = 0; mt < 2; mt++) {
        #pragma unroll
        for (int rr = 0; rr < 2; rr++) {
            int r = wm * 32 + mt * 16 + rr * 8 + g;
            float mu = mu_s[r];
            float s = 0.f;
            #pragma unroll
            for (int nt = 0; nt < 8; nt++) {
                float d0 = acc[mt][nt][rr * 2] - mu, d1 = acc[mt][nt][rr * 2 + 1] - mu;
                s += d0 * d0 + d1 * d1;
            }
            s += __shfl_xor_sync(0xffffffffu, s, 1);
            s += __shfl_xor_sync(0xffffffffu, s, 2);
            if (q == 0) redQ[r * 8 + wn] = s;
        }
    }
    __syncthreads();
    if (t < 64) iv_s[t] = rsqrtf((redQ[t * 8] + redQ[t * 8 + 1] + redQ[t * 8 + 2] + redQ[t * 8 + 3]) * (1.f / 256.f) + LN_EPS);
    __syncthreads();

    #pragma unroll
    for (int mt = 0; mt < 2; mt++) {
        #pragma unroll
        for (int rr = 0; rr < 2; rr++) {
            int r = wm * 32 + mt * 16 + rr * 8 + g;
            float mu = mu_s[r], iv = iv_s[r];
            int grow = row0 + r;
            #pragma unroll
            for (int nt = 0; nt < 8; nt++) {
                int c0 = wn * 64 + nt * 8 + q * 2;
                float y0 = (acc[mt][nt][rr * 2] - mu) * iv * g_s[c0] + b_s[c0];
                float y1 = (acc[mt][nt][rr * 2 + 1] - mu) * iv * g_s[c0 + 1] + b_s[c0 + 1];
                if (MODE2 == 0) {
                    __nv_bfloat16 h0, l0, h1, l1;
                    split_bf16(y0, h0, l0); split_bf16(y1, h1, l1);
                    *(__nv_bfloat162*)(outH + (size_t)grow * HIDN + c0) = __nv_bfloat162(h0, h1);
                    *(__nv_bfloat162*)(outL + (size_t)grow * HIDN + c0) = __nv_bfloat162(l0, l1);
                } else {
                    *(float2*)(smem + OFF_Y + (r * 264 + c0) * 4) = make_float2(y0, y1);
                }
            }
        }
    }

    if (MODE2 == 1) {
        __syncthreads();
        float* Y = (float*)(smem + OFF_Y);
        float* wt = (float*)(smem + OFF_WT);
        float* bw_s = (float*)(smem + OFF_BW);
        const size_t WOFF = (size_t)MTOK * HIDN;
        #pragma unroll
        for (int rr2 = 0; rr2 < 8; rr2++) {
            int r = wid * 8 + rr2;
            int m = row0 + r;
            float yv[8];
            #pragma unroll
            for (int i = 0; i < 8; i++) yv[i] = Y[r * 264 + lane + 32 * i];
            float lg[NVAR];
            #pragma unroll
            for (int j = 0; j < NVAR; j++) {
                float s = 0.f;
                #pragma unroll
                for (int i = 0; i < 8; i++) s += yv[i] * wt[j * 260 + lane + 32 * i];
                lg[j] = s;
            }
            #pragma unroll
            for (int j = 0; j < NVAR; j++) {
                #pragma unroll
                for (int o = 16; o > 0; o >>= 1) lg[j] += __shfl_xor_sync(0xffffffffu, lg[j], o);
                lg[j] += bw_s[j];
            }
            float mx = -1e30f;
            #pragma unroll
            for (int j = 0; j < NVAR; j++) mx = fmaxf(mx, lg[j]);
            float sum = 0.f;
            #pragma unroll
            for (int j = 0; j < NVAR; j++) { lg[j] = __expf(lg[j] - mx); sum += lg[j]; }
            float invs = 1.0f / sum;
            float myw = 0.f;
            #pragma unroll
            for (int j = 0; j < NVAR; j++) if (lane == j) myw = lg[j] * invs;
            if (lane < NVAR) outW[WOFF + (size_t)m * NVAR + lane] = myw;
        }
    }
}

// ======================= K_final: weights + x -> vs_output (float4) ==============
__global__ void k_final(const float* __restrict__ x, float* __restrict__ out) {
    int t = threadIdx.x;
    int warp = t >> 5, lane = t & 31;
    const size_t WOFF = (size_t)MTOK * HIDN;
    #pragma unroll
    for (int tk = 0; tk < 2; tk++) {
        int m = blockIdx.x * 16 + warp * 2 + tk;
        float lg[NVAR];
        #pragma unroll
        for (int j = 0; j < NVAR; j++) lg[j] = out[WOFF + (size_t)m * NVAR + j];
        const float* xb = x + (size_t)m * (NVAR * HIDN);
        int c0 = lane * 8;
        float a[8] = {};
        #pragma unroll 4
        for (int vv = 0; vv < NVAR; vv++) {
            float wv = lg[vv];
            float4 p0 = *(const float4*)(xb + vv * HIDN + c0);
            float4 p1 = *(const float4*)(xb + vv * HIDN + c0 + 4);
            a[0] += wv * p0.x; a[1] += wv * p0.y; a[2] += wv * p0.z; a[3] += wv * p0.w;
            a[4] += wv * p1.x; a[5] += wv * p1.y; a[6] += wv * p1.z; a[7] += wv * p1.w;
        }
        *(float4*)(out + (size_t)m * HIDN + c0) = make_float4(a[0], a[1], a[2], a[3]);
        *(float4*)(out + (size_t)m * HIDN + c0 + 4) = make_float4(a[4], a[5], a[6], a[7]);
    }
}

extern "C" void kernel_launch(void* const* d_in, const int* in_sizes, int n_in,
                              void* d_out, int out_size) {
    (void)in_sizes; (void)n_in; (void)out_size;
    const float* x     = (const float*)d_in[0];
    const float* cls   = (const float*)d_in[1];
    const float* wq    = (const float*)d_in[2];
    const float* bq    = (const float*)d_in[3];
    const float* wk    = (const float*)d_in[4];
    const float* bk    = (const float*)d_in[5];
    const float* wv    = (const float*)d_in[6];
    const float* bv    = (const float*)d_in[7];
    const float* wo    = (const float*)d_in[8];
    const float* bo    = (const float*)d_in[9];
    const float* ln1_g = (const float*)d_in[10];
    const float* ln1_b = (const float*)d_in[11];
    const float* w1    = (const float*)d_in[12];
    const float* b1    = (const float*)d_in[13];
    const float* w2    = (const float*)d_in[14];
    const float* b2    = (const float*)d_in[15];
    const float* ln2_g = (const float*)d_in[16];
    const float* ln2_b = (const float*)d_in[17];
    const float* ww    = (const float*)d_in[18];
    const float* bw    = (const float*)d_in[19];
    float* out = (float*)d_out;

    cudaFuncSetAttribute(k_mma_ff1, cudaFuncAttributeMaxDynamicSharedMemorySize, MM_TOTAL2);
    cudaFuncSetAttribute(k_mma_ctx, cudaFuncAttributeMaxDynamicSharedMemorySize, CT_TOTAL);
    cudaFuncSetAttribute(k_mma_w<0>, cudaFuncAttributeMaxDynamicSharedMemorySize, W_TOTAL);
    cudaFuncSetAttribute(k_mma_w<1>, cudaFuncAttributeMaxDynamicSharedMemorySize, W_TOTAL);

    void *p_ctxh, *p_ctxl, *p_h1h, *p_h1l, *p_h2h, *p_h2l, *p_cbias;
    void *p_woh, *p_wol, *p_w1h, *p_w1l, *p_w2h, *p_w2l;
    cudaGetSymbolAddress(&p_ctxh, g_ctxh);  cudaGetSymbolAddress(&p_ctxl, g_ctxl);
    cudaGetSymbolAddress(&p_h1h, g_h1h);    cudaGetSymbolAddress(&p_h1l, g_h1l);
    cudaGetSymbolAddress(&p_h2h, g_h2h);    cudaGetSymbolAddress(&p_h2l, g_h2l);
    cudaGetSymbolAddress(&p_cbias, g_cbias);
    cudaGetSymbolAddress(&p_woh, g_woT_h);  cudaGetSymbolAddress(&p_wol, g_woT_l);
    cudaGetSymbolAddress(&p_w1h, g_w1T_h);  cudaGetSymbolAddress(&p_w1l, g_w1T_l);
    cudaGetSymbolAddress(&p_w2h, g_w2T_h);  cudaGetSymbolAddress(&p_w2l, g_w2T_l);

    k_pre<<<1, 256>>>(cls, wq, bq, wk, bk, wo, bo, bv);
    k_wsplit_all<<<dim3(256, 4), 256>>>(wo, w1, w2, wv);

    k1_attn<<<MTOK, 256>>>(x);
    k_mma_ctx<<<dim3(MTOK / 128, NHEAD), 256, CT_TOTAL>>>();

    // o-proj + cbias + LN1 -> h1 hi/lo   (K=256, N=256)
    k_mma_w<0><<<MTOK / 64, 256, W_TOTAL>>>(
        (const __nv_bfloat16*)p_ctxh, (const __nv_bfloat16*)p_ctxl,
        (const __nv_bfloat16*)p_woh, (const __nv_bfloat16*)p_wol,
        (const float*)p_cbias, ln1_g, ln1_b, nullptr, nullptr,
        (__nv_bfloat16*)p_h1h, (__nv_bfloat16*)p_h1l, nullptr, HIDN);

    // FF1: h2 = gelu(h1 @ w1 + b1)    (K=256, N=1024)
    k_mma_ff1<<<dim3(FFD / 128, MTOK / 128), 256, MM_TOTAL2>>>(
        (const __nv_bfloat16*)p_h1h, (const __nv_bfloat16*)p_h1l,
        (const __nv_bfloat16*)p_w1h, (const __nv_bfloat16*)p_w1l,
        b1, (__nv_bfloat16*)p_h2h, (__nv_bfloat16*)p_h2l, HIDN, FFD);

    // FF2 + b2 + LN2 + logits + softmax -> weights   (K=1024, N=256)
    k_mma_w<1><<<MTOK / 64, 256, W_TOTAL>>>(
        (const __nv_bfloat16*)p_h2h, (const __nv_bfloat16*)p_h2l,
        (const __nv_bfloat16*)p_w2h, (const __nv_bfloat16*)p_w2l,
        b2, ln2_g, ln2_b, ww, bw, nullptr, nullptr, out, FFD);

    k_final<<<MTOK / 16, 256>>>(x, out);
}